// round 3
// baseline (speedup 1.0000x reference)
#include <cuda_runtime.h>

#define NN 50000
#define EE 800000
#define HH 256
#define BB 128
#define VV 4
#define CC 10
#define NH (NN*HH)

// ---- scratch (device globals; no allocation allowed) ----
__device__ int   g_degcnt[NN];
__device__ int   g_rowptr[NN+1];
__device__ int   g_fill[NN];
__device__ float g_invdeg[NN];
__device__ int   g_col[EE];
__device__ int   g_counts[BB];
__device__ float g_z[NH];          // (x*dropout) @ W1
__device__ float g_view[VV*NH];    // per-view propagated states
__device__ float g_tmp[NH];        // ping-pong buffer
__device__ float g_pool[VV*BB*HH]; // pooled relu(view + b1)
__device__ float g_probs[VV*BB*CC];

// ---------------------------------------------------------------------------
__global__ void k_zero() {
    int i = blockIdx.x * blockDim.x + threadIdx.x;
    if (i < NN) g_degcnt[i] = 0;
    if (i < BB) g_counts[i] = 0;
    if (i < VV*BB*HH) g_pool[i] = 0.f;
}

__global__ void k_hist(const int* __restrict__ ei) {
    int e = blockIdx.x * blockDim.x + threadIdx.x;
    if (e < EE) {
        int r = ei[e];
        if ((unsigned)r < NN) atomicAdd(&g_degcnt[r], 1);
    }
}

// chunked serial scan: 1024 threads, each owns a contiguous chunk of counts.
__global__ void k_scan() {
    __shared__ int part[1024];
    int tid = threadIdx.x;
    const int CH = (NN + 1023) / 1024;   // 49
    int lo = tid * CH;
    int hi = lo + CH; if (hi > NN) hi = NN;
    if (lo > NN) lo = NN;
    int s = 0;
    for (int i = lo; i < hi; i++) s += g_degcnt[i];
    part[tid] = s;
    __syncthreads();
    if (tid == 0) {
        int run = 0;
        for (int i = 0; i < 1024; i++) { int t = part[i]; part[i] = run; run += t; }
        g_rowptr[NN] = run;
    }
    __syncthreads();
    int run = part[tid];
    for (int i = lo; i < hi; i++) {
        int c = g_degcnt[i];
        g_rowptr[i] = run;
        g_fill[i]   = run;
        g_invdeg[i] = 1.0f / (float)(c + 1);   // +1 self loop
        run += c;
    }
}

__global__ void k_fill(const int* __restrict__ ei) {
    int e = blockIdx.x * blockDim.x + threadIdx.x;
    if (e < EE) {
        int r = ei[e];
        int c = ei[EE + e];
        if ((unsigned)r < NN && (unsigned)c < NN) {
            int p = atomicAdd(&g_fill[r], 1);
            if ((unsigned)p < EE) g_col[p] = c;
        }
    }
}

__global__ void k_counts(const int* __restrict__ batch) {
    int i = blockIdx.x * blockDim.x + threadIdx.x;
    if (i < NN) {
        int b = batch[i];
        if ((unsigned)b < BB) atomicAdd(&g_counts[b], 1);
    }
}

// ---------------------------------------------------------------------------
// z = (x * dropout_mask) @ W1    [N,256] x [256,256], fp32, 128x128x8 tiles
__global__ __launch_bounds__(256) void k_gemm(const float* __restrict__ x,
                                              const float* __restrict__ dm,
                                              const float* __restrict__ W1) {
    __shared__ float As[8][128];
    __shared__ float Bs[8][128];
    int tid = threadIdx.x;
    int br = blockIdx.y, bc = blockIdx.x;
    int tx = tid & 15, ty = tid >> 4;

    float acc[8][8];
    #pragma unroll
    for (int i = 0; i < 8; i++)
        #pragma unroll
        for (int j = 0; j < 8; j++) acc[i][j] = 0.f;

    int arow  = br * 128 + (tid >> 1);
    int acol0 = (tid & 1) * 4;
    int brow  = tid >> 5;
    int bcol  = (tid & 31) * 4;

    for (int kk = 0; kk < HH; kk += 8) {
        float4 av = make_float4(0.f, 0.f, 0.f, 0.f);
        if (arow < NN) {
            float4 xv = *(const float4*)(x  + (size_t)arow * HH + kk + acol0);
            float4 dv = *(const float4*)(dm + (size_t)arow * HH + kk + acol0);
            av = make_float4(xv.x*dv.x, xv.y*dv.y, xv.z*dv.z, xv.w*dv.w);
        }
        As[acol0+0][tid>>1] = av.x;
        As[acol0+1][tid>>1] = av.y;
        As[acol0+2][tid>>1] = av.z;
        As[acol0+3][tid>>1] = av.w;
        float4 bv = *(const float4*)(W1 + (size_t)(kk + brow) * HH + bc * 128 + bcol);
        *(float4*)&Bs[brow][bcol] = bv;
        __syncthreads();
        #pragma unroll
        for (int k = 0; k < 8; k++) {
            float rm[8], rn[8];
            #pragma unroll
            for (int i = 0; i < 8; i++) rm[i] = As[k][ty*8+i];
            #pragma unroll
            for (int j = 0; j < 8; j++) rn[j] = Bs[k][tx*8+j];
            #pragma unroll
            for (int i = 0; i < 8; i++)
                #pragma unroll
                for (int j = 0; j < 8; j++) acc[i][j] += rm[i] * rn[j];
        }
        __syncthreads();
    }
    #pragma unroll
    for (int i = 0; i < 8; i++) {
        int r = br * 128 + ty * 8 + i;
        if (r < NN) {
            float* orow = g_z + (size_t)r * HH + bc * 128 + tx * 8;
            *(float4*)(orow)     = make_float4(acc[i][0], acc[i][1], acc[i][2], acc[i][3]);
            *(float4*)(orow + 4) = make_float4(acc[i][4], acc[i][5], acc[i][6], acc[i][7]);
        }
    }
}

// ---------------------------------------------------------------------------
// Fused first propagation step for all 4 views: one gather of z[c], 4 masked accums
__global__ __launch_bounds__(256) void k_step1(const float* __restrict__ masks) {
    int gw = (blockIdx.x * blockDim.x + threadIdx.x) >> 5;
    int lane = threadIdx.x & 31;
    if (gw >= NN) return;
    int r = gw;

    const float4* zr = (const float4*)(g_z + (size_t)r * HH);
    float4 s0 = zr[lane], s1 = zr[lane + 32];

    float4 a0[VV], a1[VV];
    #pragma unroll
    for (int v = 0; v < VV; v++) {
        float m = masks[v * NN + r];            // self loop contribution
        a0[v] = make_float4(s0.x*m, s0.y*m, s0.z*m, s0.w*m);
        a1[v] = make_float4(s1.x*m, s1.y*m, s1.z*m, s1.w*m);
    }

    int jb = g_rowptr[r], je = g_rowptr[r + 1];
    for (int j = jb; j < je; j++) {
        int c = g_col[j];
        const float4* zc = (const float4*)(g_z + (size_t)c * HH);
        float4 c0 = zc[lane], c1 = zc[lane + 32];
        #pragma unroll
        for (int v = 0; v < VV; v++) {
            float m = masks[v * NN + c];
            a0[v].x += m*c0.x; a0[v].y += m*c0.y; a0[v].z += m*c0.z; a0[v].w += m*c0.w;
            a1[v].x += m*c1.x; a1[v].y += m*c1.y; a1[v].z += m*c1.z; a1[v].w += m*c1.w;
        }
    }
    float inv = g_invdeg[r];
    #pragma unroll
    for (int v = 0; v < VV; v++) {
        float4* orow = (float4*)(g_view + (size_t)v * NH + (size_t)r * HH);
        orow[lane]      = make_float4(a0[v].x*inv, a0[v].y*inv, a0[v].z*inv, a0[v].w*inv);
        orow[lane + 32] = make_float4(a1[v].x*inv, a1[v].y*inv, a1[v].z*inv, a1[v].w*inv);
    }
}

// one propagation step for one view; sel<VV selects g_view[sel], sel==VV selects g_tmp
__global__ __launch_bounds__(256) void k_spmm(int in_sel, int out_sel) {
    const float* in = (in_sel < VV) ? (g_view + (size_t)in_sel * NH) : g_tmp;
    float* out      = (out_sel < VV) ? (g_view + (size_t)out_sel * NH) : g_tmp;

    int gw = (blockIdx.x * blockDim.x + threadIdx.x) >> 5;
    int lane = threadIdx.x & 31;
    if (gw >= NN) return;
    int r = gw;

    const float4* ir = (const float4*)(in + (size_t)r * HH);
    float4 a0 = ir[lane], a1 = ir[lane + 32];    // self loop

    int jb = g_rowptr[r], je = g_rowptr[r + 1];
    int j = jb;
    for (; j + 1 < je; j += 2) {
        int c0i = g_col[j], c1i = g_col[j + 1];
        const float4* p0 = (const float4*)(in + (size_t)c0i * HH);
        const float4* p1 = (const float4*)(in + (size_t)c1i * HH);
        float4 u0 = p0[lane], u1 = p0[lane + 32];
        float4 w0 = p1[lane], w1 = p1[lane + 32];
        a0.x += u0.x + w0.x; a0.y += u0.y + w0.y; a0.z += u0.z + w0.z; a0.w += u0.w + w0.w;
        a1.x += u1.x + w1.x; a1.y += u1.y + w1.y; a1.z += u1.z + w1.z; a1.w += u1.w + w1.w;
    }
    if (j < je) {
        int c = g_col[j];
        const float4* p = (const float4*)(in + (size_t)c * HH);
        float4 u0 = p[lane], u1 = p[lane + 32];
        a0.x += u0.x; a0.y += u0.y; a0.z += u0.z; a0.w += u0.w;
        a1.x += u1.x; a1.y += u1.y; a1.z += u1.z; a1.w += u1.w;
    }
    float inv = g_invdeg[r];
    float4* orow = (float4*)(out + (size_t)r * HH);
    orow[lane]      = make_float4(a0.x*inv, a0.y*inv, a0.z*inv, a0.w*inv);
    orow[lane + 32] = make_float4(a1.x*inv, a1.y*inv, a1.z*inv, a1.w*inv);
}

// ---------------------------------------------------------------------------
// pooled[v][b][f] = sum over nodes r with batch[r]==b of relu(view_v[r][f] + b1[f])
// batch is sorted -> per-block run-length accumulation, few atomics
__global__ __launch_bounds__(256) void k_pool(const int* __restrict__ batch,
                                              const float* __restrict__ b1) {
    int v  = blockIdx.y;
    int f  = threadIdx.x;
    int r0 = blockIdx.x * 64;
    const float* in = g_view + (size_t)v * NH;
    float bias = b1[f];
    float acc = 0.f;
    int curb = -1;
    int rend = r0 + 64; if (rend > NN) rend = NN;
    for (int r = r0; r < rend; r++) {
        int b = batch[r];
        if ((unsigned)b >= BB) continue;
        if (b != curb) {
            if (curb >= 0) atomicAdd(&g_pool[(curb + v * BB) * HH + f], acc);
            acc = 0.f; curb = b;
        }
        float val = in[(size_t)r * HH + f] + bias;
        acc += fmaxf(val, 0.f);
    }
    if (curb >= 0) atomicAdd(&g_pool[(curb + v * BB) * HH + f], acc);
}

// head: per (v,b): y = (pool/cnt)@W2 + b2; logits = y@Wc + bc; softmax -> probs
__global__ __launch_bounds__(256) void k_head(const float* __restrict__ W2,
                                              const float* __restrict__ b2,
                                              const float* __restrict__ Wc,
                                              const float* __restrict__ bcv,
                                              float* __restrict__ out) {
    __shared__ float sp[HH];
    __shared__ float sy[HH];
    __shared__ float slog[CC];
    int vb = blockIdx.x;
    int v = vb >> 7, b = vb & 127;
    int tid = threadIdx.x;

    float cnt = (float)g_counts[b];
    if (cnt < 1.f) cnt = 1.f;
    sp[tid] = g_pool[(v * BB + b) * HH + tid] / cnt;
    __syncthreads();

    float acc = b2[tid];
    #pragma unroll 8
    for (int h = 0; h < HH; h++) acc += sp[h] * W2[h * HH + tid];
    sy[tid] = acc;
    __syncthreads();

    if (tid < CC) {
        float l = bcv[tid];
        #pragma unroll 8
        for (int h = 0; h < HH; h++) l += sy[h] * Wc[h * CC + tid];
        slog[tid] = l;
    }
    __syncthreads();

    if (tid == 0) {
        float mx = -1e30f;
        #pragma unroll
        for (int c = 0; c < CC; c++) mx = fmaxf(mx, slog[c]);
        float s = 0.f, e[CC];
        #pragma unroll
        for (int c = 0; c < CC; c++) { e[c] = expf(slog[c] - mx); s += e[c]; }
        float invs = 1.f / s;
        #pragma unroll
        for (int c = 0; c < CC; c++) g_probs[(v * BB + b) * CC + c] = e[c] * invs;
        if (v == 0) {
            #pragma unroll
            for (int c = 0; c < CC; c++) out[b * CC + c] = slog[c];
        }
    }
}

__global__ void k_loss(float* __restrict__ out, int out_size) {
    __shared__ float sc[BB], se[BB];
    int b = threadIdx.x;
    float mp[CC];
    #pragma unroll
    for (int c = 0; c < CC; c++) {
        float s = 0.f;
        #pragma unroll
        for (int v = 0; v < VV; v++) s += g_probs[(v * BB + b) * CC + c];
        mp[c] = s * (1.0f / VV);
    }
    float cons = 0.f;
    #pragma unroll
    for (int v = 0; v < VV; v++)
        #pragma unroll
        for (int c = 0; c < CC; c++) {
            float d = g_probs[(v * BB + b) * CC + c] - mp[c];
            cons += d * d;
        }
    float ent = 0.f;
    #pragma unroll
    for (int c = 0; c < CC; c++) ent -= mp[c] * logf(mp[c] + 1e-8f);
    sc[b] = cons; se[b] = ent;
    __syncthreads();
    for (int s = 64; s > 0; s >>= 1) {
        if (b < s) { sc[b] += sc[b + s]; se[b] += se[b + s]; }
        __syncthreads();
    }
    if (b == 0)
        out[out_size - 1] = 1.0f * (sc[0] / (float)(VV * BB)) + se[0] / (float)BB;
}

// ---------------------------------------------------------------------------
extern "C" void kernel_launch(void* const* d_in, const int* in_sizes, int n_in,
                              void* d_out, int out_size) {
    const float* x     = (const float*)d_in[0];
    const int*   ei    = (const int*)d_in[1];
    const int*   batch = (const int*)d_in[2];
    const float* dm    = (const float*)d_in[3];
    const float* masks = (const float*)d_in[4];
    const float* W1    = (const float*)d_in[5];
    const float* b1    = (const float*)d_in[6];
    const float* W2    = (const float*)d_in[7];
    const float* b2    = (const float*)d_in[8];
    const float* Wc    = (const float*)d_in[9];
    const float* bcv   = (const float*)d_in[10];
    float* out = (float*)d_out;

    k_zero  <<<(VV*BB*HH + 255) / 256, 256>>>();
    k_hist  <<<(EE + 255) / 256, 256>>>(ei);
    k_scan  <<<1, 1024>>>();
    k_fill  <<<(EE + 255) / 256, 256>>>(ei);
    k_counts<<<(NN + 255) / 256, 256>>>(batch);

    dim3 ggrid(2, (NN + 127) / 128);
    k_gemm<<<ggrid, 256>>>(x, dm, W1);

    int wgrid = (NN * 32 + 255) / 256;
    k_step1<<<wgrid, 256>>>(masks);
    for (int v = 0; v < VV; v++) {
        k_spmm<<<wgrid, 256>>>(v, VV);   // step 2: view -> tmp
        k_spmm<<<wgrid, 256>>>(VV, v);   // step 3: tmp -> view
    }

    dim3 pgrid((NN + 63) / 64, VV);
    k_pool<<<pgrid, 256>>>(batch, b1);

    k_head<<<VV * BB, 256>>>(W2, b2, Wc, bcv, out);
    k_loss<<<1, BB>>>(out, out_size);
}

// round 5
// speedup vs baseline: 1.2147x; 1.2147x over previous
#include <cuda_runtime.h>
#include <cuda_fp16.h>

#define NN 50000
#define EE 800000
#define HH 256
#define BB 128
#define VV 4
#define CC 10
#define NH (NN*HH)

// ---- scratch (device globals; no allocation allowed) ----
__device__ int    g_degcnt[NN];
__device__ int    g_rowptr[NN+1];
__device__ int    g_fill[NN];
__device__ float  g_invdeg[NN];
__device__ int    g_col[EE];
__device__ int    g_counts[BB];
__device__ __half g_z[NH];           // (x*dropout) @ W1, fp16 storage
__device__ __half g_view[VV*NH];     // per-view propagated states
__device__ __half g_tmp[NH];         // ping-pong buffer
__device__ float  g_pool[VV*BB*HH];  // pooled relu(view + b1)
__device__ float  g_probs[VV*BB*CC];

// ---------------------------------------------------------------------------
__global__ void k_zero() {
    int i = blockIdx.x * blockDim.x + threadIdx.x;
    if (i < NN) g_degcnt[i] = 0;
    if (i < BB) g_counts[i] = 0;
    if (i < VV*BB*HH) g_pool[i] = 0.f;
}

__global__ void k_hist(const int* __restrict__ ei) {
    int e = blockIdx.x * blockDim.x + threadIdx.x;
    if (e < EE) {
        int r = ei[e];
        if ((unsigned)r < NN) atomicAdd(&g_degcnt[r], 1);
    }
}

// chunked serial scan: 1024 threads, each owns a contiguous chunk of counts.
__global__ void k_scan() {
    __shared__ int part[1024];
    int tid = threadIdx.x;
    const int CH = (NN + 1023) / 1024;   // 49
    int lo = tid * CH;
    int hi = lo + CH; if (hi > NN) hi = NN;
    if (lo > NN) lo = NN;
    int s = 0;
    for (int i = lo; i < hi; i++) s += g_degcnt[i];
    part[tid] = s;
    __syncthreads();
    if (tid == 0) {
        int run = 0;
        for (int i = 0; i < 1024; i++) { int t = part[i]; part[i] = run; run += t; }
        g_rowptr[NN] = run;
    }
    __syncthreads();
    int run = part[tid];
    for (int i = lo; i < hi; i++) {
        int c = g_degcnt[i];
        g_rowptr[i] = run;
        g_fill[i]   = run;
        g_invdeg[i] = 1.0f / (float)(c + 1);   // +1 self loop
        run += c;
    }
}

__global__ void k_fill(const int* __restrict__ ei) {
    int e = blockIdx.x * blockDim.x + threadIdx.x;
    if (e < EE) {
        int r = ei[e];
        int c = ei[EE + e];
        if ((unsigned)r < NN && (unsigned)c < NN) {
            int p = atomicAdd(&g_fill[r], 1);
            if ((unsigned)p < EE) g_col[p] = c;
        }
    }
}

__global__ void k_counts(const int* __restrict__ batch) {
    int i = blockIdx.x * blockDim.x + threadIdx.x;
    if (i < NN) {
        int b = batch[i];
        if ((unsigned)b < BB) atomicAdd(&g_counts[b], 1);
    }
}

// ---------------------------------------------------------------------------
// z = (x * dropout_mask) @ W1    [N,256] x [256,256], fp32 math, fp16 output
__global__ __launch_bounds__(256) void k_gemm(const float* __restrict__ x,
                                              const float* __restrict__ dm,
                                              const float* __restrict__ W1) {
    __shared__ float As[8][128];
    __shared__ float Bs[8][128];
    int tid = threadIdx.x;
    int br = blockIdx.y, bc = blockIdx.x;
    int tx = tid & 15, ty = tid >> 4;

    float acc[8][8];
    #pragma unroll
    for (int i = 0; i < 8; i++)
        #pragma unroll
        for (int j = 0; j < 8; j++) acc[i][j] = 0.f;

    int arow  = br * 128 + (tid >> 1);
    int acol0 = (tid & 1) * 4;
    int brow  = tid >> 5;
    int bcol  = (tid & 31) * 4;

    for (int kk = 0; kk < HH; kk += 8) {
        float4 av = make_float4(0.f, 0.f, 0.f, 0.f);
        if (arow < NN) {
            float4 xv = *(const float4*)(x  + (size_t)arow * HH + kk + acol0);
            float4 dv = *(const float4*)(dm + (size_t)arow * HH + kk + acol0);
            av = make_float4(xv.x*dv.x, xv.y*dv.y, xv.z*dv.z, xv.w*dv.w);
        }
        As[acol0+0][tid>>1] = av.x;
        As[acol0+1][tid>>1] = av.y;
        As[acol0+2][tid>>1] = av.z;
        As[acol0+3][tid>>1] = av.w;
        float4 bv = *(const float4*)(W1 + (size_t)(kk + brow) * HH + bc * 128 + bcol);
        *(float4*)&Bs[brow][bcol] = bv;
        __syncthreads();
        #pragma unroll
        for (int k = 0; k < 8; k++) {
            float rm[8], rn[8];
            #pragma unroll
            for (int i = 0; i < 8; i++) rm[i] = As[k][ty*8+i];
            #pragma unroll
            for (int j = 0; j < 8; j++) rn[j] = Bs[k][tx*8+j];
            #pragma unroll
            for (int i = 0; i < 8; i++)
                #pragma unroll
                for (int j = 0; j < 8; j++) acc[i][j] += rm[i] * rn[j];
        }
        __syncthreads();
    }
    #pragma unroll
    for (int i = 0; i < 8; i++) {
        int r = br * 128 + ty * 8 + i;
        if (r < NN) {
            __half2 h[4];
            #pragma unroll
            for (int p = 0; p < 4; p++)
                h[p] = __floats2half2_rn(acc[i][2*p], acc[i][2*p+1]);
            *(uint4*)(g_z + (size_t)r * HH + bc * 128 + tx * 8) = *(uint4*)h;  // FIX: full 16B
        }
    }
}

// ---------------------------------------------------------------------------
// helpers: each lane owns 8 consecutive halves (one 16B load) of a 256-wide row
__device__ __forceinline__ void load_row8(const __half* base, int lane, float f[8]) {
    uint4 raw = ((const uint4*)base)[lane];
    __half2* h = (__half2*)&raw;
    float2 t;
    t = __half22float2(h[0]); f[0] = t.x; f[1] = t.y;
    t = __half22float2(h[1]); f[2] = t.x; f[3] = t.y;
    t = __half22float2(h[2]); f[4] = t.x; f[5] = t.y;
    t = __half22float2(h[3]); f[6] = t.x; f[7] = t.y;
}
__device__ __forceinline__ void store_row8(__half* base, int lane, const float f[8], float scale) {
    __half2 h[4];
    #pragma unroll
    for (int p = 0; p < 4; p++)
        h[p] = __floats2half2_rn(f[2*p] * scale, f[2*p+1] * scale);
    ((uint4*)base)[lane] = *(uint4*)h;
}

// Fused first propagation step for all 4 views: one gather of z[c], 4 masked accums
__global__ __launch_bounds__(256) void k_step1(const float* __restrict__ masks) {
    int gw = (blockIdx.x * blockDim.x + threadIdx.x) >> 5;
    int lane = threadIdx.x & 31;
    if (gw >= NN) return;
    int r = gw;

    float s[8];
    load_row8(g_z + (size_t)r * HH, lane, s);

    float a[VV][8];
    #pragma unroll
    for (int v = 0; v < VV; v++) {
        float m = masks[v * NN + r];            // self loop contribution
        #pragma unroll
        for (int q = 0; q < 8; q++) a[v][q] = s[q] * m;
    }

    int jb = g_rowptr[r], je = g_rowptr[r + 1];
    for (int j = jb; j < je; j++) {
        int c = g_col[j];
        float cf[8];
        load_row8(g_z + (size_t)c * HH, lane, cf);
        #pragma unroll
        for (int v = 0; v < VV; v++) {
            float m = masks[v * NN + c];
            #pragma unroll
            for (int q = 0; q < 8; q++) a[v][q] += m * cf[q];
        }
    }
    float inv = g_invdeg[r];
    #pragma unroll
    for (int v = 0; v < VV; v++)
        store_row8(g_view + (size_t)v * NH + (size_t)r * HH, lane, a[v], inv);
}

// one propagation step for one view; sel<VV selects g_view[sel], sel==VV selects g_tmp
__global__ __launch_bounds__(256) void k_spmm(int in_sel, int out_sel) {
    const __half* in = (in_sel < VV) ? (g_view + (size_t)in_sel * NH) : g_tmp;
    __half* out      = (out_sel < VV) ? (g_view + (size_t)out_sel * NH) : g_tmp;

    int gw = (blockIdx.x * blockDim.x + threadIdx.x) >> 5;
    int lane = threadIdx.x & 31;
    if (gw >= NN) return;
    int r = gw;

    float a[8];
    load_row8(in + (size_t)r * HH, lane, a);    // self loop

    int jb = g_rowptr[r], je = g_rowptr[r + 1];
    int j = jb;
    for (; j + 1 < je; j += 2) {
        int c0 = g_col[j], c1 = g_col[j + 1];
        float u[8], w[8];
        load_row8(in + (size_t)c0 * HH, lane, u);
        load_row8(in + (size_t)c1 * HH, lane, w);
        #pragma unroll
        for (int q = 0; q < 8; q++) a[q] += u[q] + w[q];
    }
    if (j < je) {
        int c = g_col[j];
        float u[8];
        load_row8(in + (size_t)c * HH, lane, u);
        #pragma unroll
        for (int q = 0; q < 8; q++) a[q] += u[q];
    }
    store_row8(out + (size_t)r * HH, lane, a, g_invdeg[r]);
}

// ---------------------------------------------------------------------------
// pooled[v][b][f] = sum over nodes r with batch[r]==b of relu(view_v[r][f] + b1[f])
__global__ __launch_bounds__(256) void k_pool(const int* __restrict__ batch,
                                              const float* __restrict__ b1) {
    int v  = blockIdx.y;
    int f  = threadIdx.x;
    int r0 = blockIdx.x * 64;
    const __half* in = g_view + (size_t)v * NH;
    float bias = b1[f];
    float acc = 0.f;
    int curb = -1;
    int rend = r0 + 64; if (rend > NN) rend = NN;
    for (int r = r0; r < rend; r++) {
        int b = batch[r];
        if ((unsigned)b >= BB) continue;
        if (b != curb) {
            if (curb >= 0) atomicAdd(&g_pool[(curb + v * BB) * HH + f], acc);
            acc = 0.f; curb = b;
        }
        float val = __half2float(in[(size_t)r * HH + f]) + bias;
        acc += fmaxf(val, 0.f);
    }
    if (curb >= 0) atomicAdd(&g_pool[(curb + v * BB) * HH + f], acc);
}

// head: per (v,b): y = (pool/cnt)@W2 + b2; logits = y@Wc + bc; softmax -> probs
__global__ __launch_bounds__(256) void k_head(const float* __restrict__ W2,
                                              const float* __restrict__ b2,
                                              const float* __restrict__ Wc,
                                              const float* __restrict__ bcv,
                                              float* __restrict__ out) {
    __shared__ float sp[HH];
    __shared__ float sy[HH];
    __shared__ float slog[CC];
    int vb = blockIdx.x;
    int v = vb >> 7, b = vb & 127;
    int tid = threadIdx.x;

    float cnt = (float)g_counts[b];
    if (cnt < 1.f) cnt = 1.f;
    sp[tid] = g_pool[(v * BB + b) * HH + tid] / cnt;
    __syncthreads();

    float acc = b2[tid];
    #pragma unroll 8
    for (int h = 0; h < HH; h++) acc += sp[h] * W2[h * HH + tid];
    sy[tid] = acc;
    __syncthreads();

    if (tid < CC) {
        float l = bcv[tid];
        #pragma unroll 8
        for (int h = 0; h < HH; h++) l += sy[h] * Wc[h * CC + tid];
        slog[tid] = l;
    }
    __syncthreads();

    if (tid == 0) {
        float mx = -1e30f;
        #pragma unroll
        for (int c = 0; c < CC; c++) mx = fmaxf(mx, slog[c]);
        float s = 0.f, e[CC];
        #pragma unroll
        for (int c = 0; c < CC; c++) { e[c] = expf(slog[c] - mx); s += e[c]; }
        float invs = 1.f / s;
        #pragma unroll
        for (int c = 0; c < CC; c++) g_probs[(v * BB + b) * CC + c] = e[c] * invs;
        if (v == 0) {
            #pragma unroll
            for (int c = 0; c < CC; c++) out[b * CC + c] = slog[c];
        }
    }
}

__global__ void k_loss(float* __restrict__ out, int out_size) {
    __shared__ float sc[BB], se[BB];
    int b = threadIdx.x;
    float mp[CC];
    #pragma unroll
    for (int c = 0; c < CC; c++) {
        float s = 0.f;
        #pragma unroll
        for (int v = 0; v < VV; v++) s += g_probs[(v * BB + b) * CC + c];
        mp[c] = s * (1.0f / VV);
    }
    float cons = 0.f;
    #pragma unroll
    for (int v = 0; v < VV; v++)
        #pragma unroll
        for (int c = 0; c < CC; c++) {
            float d = g_probs[(v * BB + b) * CC + c] - mp[c];
            cons += d * d;
        }
    float ent = 0.f;
    #pragma unroll
    for (int c = 0; c < CC; c++) ent -= mp[c] * logf(mp[c] + 1e-8f);
    sc[b] = cons; se[b] = ent;
    __syncthreads();
    for (int s = 64; s > 0; s >>= 1) {
        if (b < s) { sc[b] += sc[b + s]; se[b] += se[b + s]; }
        __syncthreads();
    }
    if (b == 0)
        out[out_size - 1] = 1.0f * (sc[0] / (float)(VV * BB)) + se[0] / (float)BB;
}

// ---------------------------------------------------------------------------
extern "C" void kernel_launch(void* const* d_in, const int* in_sizes, int n_in,
                              void* d_out, int out_size) {
    const float* x     = (const float*)d_in[0];
    const int*   ei    = (const int*)d_in[1];
    const int*   batch = (const int*)d_in[2];
    const float* dm    = (const float*)d_in[3];
    const float* masks = (const float*)d_in[4];
    const float* W1    = (const float*)d_in[5];
    const float* b1    = (const float*)d_in[6];
    const float* W2    = (const float*)d_in[7];
    const float* b2    = (const float*)d_in[8];
    const float* Wc    = (const float*)d_in[9];
    const float* bcv   = (const float*)d_in[10];
    float* out = (float*)d_out;

    k_zero  <<<(VV*BB*HH + 255) / 256, 256>>>();
    k_hist  <<<(EE + 255) / 256, 256>>>(ei);
    k_scan  <<<1, 1024>>>();
    k_fill  <<<(EE + 255) / 256, 256>>>(ei);
    k_counts<<<(NN + 255) / 256, 256>>>(batch);

    dim3 ggrid(2, (NN + 127) / 128);
    k_gemm<<<ggrid, 256>>>(x, dm, W1);

    int wgrid = (NN * 32 + 255) / 256;
    k_step1<<<wgrid, 256>>>(masks);
    for (int v = 0; v < VV; v++) {
        k_spmm<<<wgrid, 256>>>(v, VV);   // step 2: view -> tmp
        k_spmm<<<wgrid, 256>>>(VV, v);   // step 3: tmp -> view
    }

    dim3 pgrid((NN + 63) / 64, VV);
    k_pool<<<pgrid, 256>>>(batch, b1);

    k_head<<<VV * BB, 256>>>(W2, b2, Wc, bcv, out);
    k_loss<<<1, BB>>>(out, out_size);
}

// round 6
// speedup vs baseline: 1.3139x; 1.0816x over previous
#include <cuda_runtime.h>
#include <cuda_fp16.h>
#include <mma.h>
using namespace nvcuda;

#define NN 50000
#define NPAD 50048            // 391 * 128, pad for wmma tiles
#define EE 800000
#define HH 256
#define BB 128
#define VV 4
#define CC 10
#define NH (NN*HH)
#define VH (VV*HH)            // 1024: interleaved row width per node

// ---- scratch (device globals; no allocation allowed) ----
__device__ int    g_degcnt[NN];
__device__ int    g_rowptr[NN+1];
__device__ int    g_fill[NN];
__device__ float  g_invdeg[NN];
__device__ int    g_col[EE];
__device__ int    g_counts[BB];
__device__ __half g_xh[NPAD*HH];      // (x*dropout) fp16, zero-padded rows
__device__ __half g_w1h[HH*HH];       // W1 fp16
__device__ __half g_z[NPAD*HH];       // (x*dropout) @ W1, fp16
__device__ __half g_viewI[(size_t)NN*VH];  // interleaved [node][view][feat]
__device__ __half g_tmpI[(size_t)NN*VH];   // ping-pong
__device__ float  g_pool[VV*BB*HH];
__device__ float  g_probs[VV*BB*CC];

// ---------------------------------------------------------------------------
__global__ void k_zero() {
    int i = blockIdx.x * blockDim.x + threadIdx.x;
    if (i < NN) g_degcnt[i] = 0;
    if (i < BB) g_counts[i] = 0;
    if (i < VV*BB*HH) g_pool[i] = 0.f;
}

__global__ void k_hist(const int* __restrict__ ei) {
    int e = blockIdx.x * blockDim.x + threadIdx.x;
    if (e < EE) {
        int r = ei[e];
        if ((unsigned)r < NN) atomicAdd(&g_degcnt[r], 1);
    }
}

__global__ void k_scan() {
    __shared__ int part[1024];
    int tid = threadIdx.x;
    const int CH = (NN + 1023) / 1024;
    int lo = tid * CH;
    int hi = lo + CH; if (hi > NN) hi = NN;
    if (lo > NN) lo = NN;
    int s = 0;
    for (int i = lo; i < hi; i++) s += g_degcnt[i];
    part[tid] = s;
    __syncthreads();
    if (tid == 0) {
        int run = 0;
        for (int i = 0; i < 1024; i++) { int t = part[i]; part[i] = run; run += t; }
        g_rowptr[NN] = run;
    }
    __syncthreads();
    int run = part[tid];
    for (int i = lo; i < hi; i++) {
        int c = g_degcnt[i];
        g_rowptr[i] = run;
        g_fill[i]   = run;
        g_invdeg[i] = 1.0f / (float)(c + 1);
        run += c;
    }
}

__global__ void k_fill(const int* __restrict__ ei) {
    int e = blockIdx.x * blockDim.x + threadIdx.x;
    if (e < EE) {
        int r = ei[e];
        int c = ei[EE + e];
        if ((unsigned)r < NN && (unsigned)c < NN) {
            int p = atomicAdd(&g_fill[r], 1);
            if ((unsigned)p < EE) g_col[p] = c;
        }
    }
}

__global__ void k_counts(const int* __restrict__ batch) {
    int i = blockIdx.x * blockDim.x + threadIdx.x;
    if (i < NN) {
        int b = batch[i];
        if ((unsigned)b < BB) atomicAdd(&g_counts[b], 1);
    }
}

// ---------------------------------------------------------------------------
// fp32 -> fp16 conversions
__global__ void k_convA(const float* __restrict__ x, const float* __restrict__ dm) {
    int i = blockIdx.x * blockDim.x + threadIdx.x;   // one float4 group
    int base = i * 4;
    if (base >= NPAD*HH) return;
    __half2 h[2];
    if (base < NN*HH) {
        float4 xv = *(const float4*)(x + base);
        float4 dv = *(const float4*)(dm + base);
        h[0] = __floats2half2_rn(xv.x*dv.x, xv.y*dv.y);
        h[1] = __floats2half2_rn(xv.z*dv.z, xv.w*dv.w);
    } else {
        h[0] = __floats2half2_rn(0.f, 0.f);
        h[1] = h[0];
    }
    *(uint2*)(g_xh + base) = *(uint2*)h;
}

__global__ void k_convW(const float* __restrict__ W1) {
    int i = blockIdx.x * blockDim.x + threadIdx.x;
    int base = i * 4;
    if (base >= HH*HH) return;
    float4 w = *(const float4*)(W1 + base);
    __half2 h[2];
    h[0] = __floats2half2_rn(w.x, w.y);
    h[1] = __floats2half2_rn(w.z, w.w);
    *(uint2*)(g_w1h + base) = *(uint2*)h;
}

// ---------------------------------------------------------------------------
// z = g_xh @ g_w1h  via wmma fp16 (fp32 accum). Block 128x64 tile, 8 warps 4x2,
// each warp 32x32 (2x2 fragments). Fragments loaded straight from global.
__global__ __launch_bounds__(256) void k_gemm_wmma() {
    __shared__ float stage[8][32][36];
    int warp = threadIdx.x >> 5;
    int lane = threadIdx.x & 31;
    int wm = warp >> 1, wn = warp & 1;
    int m0 = blockIdx.y * 128 + wm * 32;
    int n0 = blockIdx.x * 64 + wn * 32;

    wmma::fragment<wmma::accumulator, 16, 16, 16, float> c[2][2];
    #pragma unroll
    for (int i = 0; i < 2; i++)
        #pragma unroll
        for (int j = 0; j < 2; j++) wmma::fill_fragment(c[i][j], 0.f);

    for (int k = 0; k < HH; k += 16) {
        wmma::fragment<wmma::matrix_a, 16, 16, 16, __half, wmma::row_major> a[2];
        wmma::fragment<wmma::matrix_b, 16, 16, 16, __half, wmma::row_major> b[2];
        #pragma unroll
        for (int i = 0; i < 2; i++)
            wmma::load_matrix_sync(a[i], g_xh + (size_t)(m0 + 16*i) * HH + k, HH);
        #pragma unroll
        for (int j = 0; j < 2; j++)
            wmma::load_matrix_sync(b[j], g_w1h + (size_t)k * HH + n0 + 16*j, HH);
        #pragma unroll
        for (int i = 0; i < 2; i++)
            #pragma unroll
            for (int j = 0; j < 2; j++)
                wmma::mma_sync(c[i][j], a[i], b[j], c[i][j]);
    }

    #pragma unroll
    for (int i = 0; i < 2; i++)
        #pragma unroll
        for (int j = 0; j < 2; j++)
            wmma::store_matrix_sync(&stage[warp][16*i][16*j], c[i][j], 36, wmma::mem_row_major);
    __syncwarp();

    // lane l writes its 32-col row: convert to half, 64B contiguous
    const float* srow = &stage[warp][lane][0];
    __half2 h[16];
    #pragma unroll
    for (int p = 0; p < 16; p++)
        h[p] = __floats2half2_rn(srow[2*p], srow[2*p+1]);
    __half* dst = g_z + (size_t)(m0 + lane) * HH + n0;
    #pragma unroll
    for (int p = 0; p < 4; p++)
        ((uint4*)dst)[p] = ((uint4*)h)[p];
}

// ---------------------------------------------------------------------------
__device__ __forceinline__ void load_row8(const __half* base, int lane, float f[8]) {
    uint4 raw = ((const uint4*)base)[lane];
    __half2* h = (__half2*)&raw;
    float2 t;
    t = __half22float2(h[0]); f[0] = t.x; f[1] = t.y;
    t = __half22float2(h[1]); f[2] = t.x; f[3] = t.y;
    t = __half22float2(h[2]); f[4] = t.x; f[5] = t.y;
    t = __half22float2(h[3]); f[6] = t.x; f[7] = t.y;
}
__device__ __forceinline__ void store_row8(__half* base, int lane, const float f[8], float scale) {
    __half2 h[4];
    #pragma unroll
    for (int p = 0; p < 4; p++)
        h[p] = __floats2half2_rn(f[2*p] * scale, f[2*p+1] * scale);
    ((uint4*)base)[lane] = *(uint4*)h;
}

// Fused first propagation step for all 4 views; writes interleaved layout.
__global__ __launch_bounds__(256) void k_step1(const float* __restrict__ masks) {
    int gw = (blockIdx.x * blockDim.x + threadIdx.x) >> 5;
    int lane = threadIdx.x & 31;
    if (gw >= NN) return;
    int r = gw;

    float s[8];
    load_row8(g_z + (size_t)r * HH, lane, s);

    float a[VV][8];
    #pragma unroll
    for (int v = 0; v < VV; v++) {
        float m = masks[v * NN + r];
        #pragma unroll
        for (int q = 0; q < 8; q++) a[v][q] = s[q] * m;
    }

    int jb = g_rowptr[r], je = g_rowptr[r + 1];
    for (int j = jb; j < je; j++) {
        int c = g_col[j];
        float cf[8];
        load_row8(g_z + (size_t)c * HH, lane, cf);
        #pragma unroll
        for (int v = 0; v < VV; v++) {
            float m = masks[v * NN + c];
            #pragma unroll
            for (int q = 0; q < 8; q++) a[v][q] += m * cf[q];
        }
    }
    float inv = g_invdeg[r];
    __half* orow = g_viewI + (size_t)r * VH;
    #pragma unroll
    for (int v = 0; v < VV; v++)
        store_row8(orow + v * HH, lane, a[v], inv);
}

// Fused propagation step for all 4 views: dir=0 viewI->tmpI, dir=1 tmpI->viewI
__global__ __launch_bounds__(256) void k_spmm4(int dir) {
    const __half* in = dir ? g_tmpI : g_viewI;
    __half* out      = dir ? g_viewI : g_tmpI;

    int gw = (blockIdx.x * blockDim.x + threadIdx.x) >> 5;
    int lane = threadIdx.x & 31;
    if (gw >= NN) return;
    int r = gw;

    float a[VV][8];
    const __half* srow = in + (size_t)r * VH;
    #pragma unroll
    for (int v = 0; v < VV; v++)
        load_row8(srow + v * HH, lane, a[v]);   // self loop

    int jb = g_rowptr[r], je = g_rowptr[r + 1];
    for (int j = jb; j < je; j++) {
        int c = g_col[j];
        const __half* crow = in + (size_t)c * VH;
        float u[VV][8];
        #pragma unroll
        for (int v = 0; v < VV; v++)
            load_row8(crow + v * HH, lane, u[v]);
        #pragma unroll
        for (int v = 0; v < VV; v++)
            #pragma unroll
            for (int q = 0; q < 8; q++) a[v][q] += u[v][q];
    }
    float inv = g_invdeg[r];
    __half* orow = out + (size_t)r * VH;
    #pragma unroll
    for (int v = 0; v < VV; v++)
        store_row8(orow + v * HH, lane, a[v], inv);
}

// ---------------------------------------------------------------------------
// pooled[v][b][f] += relu(viewI[r][v][f] + b1[f]) for batch[r]==b
__global__ __launch_bounds__(256) void k_pool(const int* __restrict__ batch,
                                              const float* __restrict__ b1) {
    int v  = blockIdx.y;
    int f  = threadIdx.x;
    int r0 = blockIdx.x * 64;
    float bias = b1[f];
    float acc = 0.f;
    int curb = -1;
    int rend = r0 + 64; if (rend > NN) rend = NN;
    for (int r = r0; r < rend; r++) {
        int b = batch[r];
        if ((unsigned)b >= BB) continue;
        if (b != curb) {
            if (curb >= 0) atomicAdd(&g_pool[(curb + v * BB) * HH + f], acc);
            acc = 0.f; curb = b;
        }
        float val = __half2float(g_viewI[(size_t)r * VH + v * HH + f]) + bias;
        acc += fmaxf(val, 0.f);
    }
    if (curb >= 0) atomicAdd(&g_pool[(curb + v * BB) * HH + f], acc);
}

__global__ __launch_bounds__(256) void k_head(const float* __restrict__ W2,
                                              const float* __restrict__ b2,
                                              const float* __restrict__ Wc,
                                              const float* __restrict__ bcv,
                                              float* __restrict__ out) {
    __shared__ float sp[HH];
    __shared__ float sy[HH];
    __shared__ float slog[CC];
    int vb = blockIdx.x;
    int v = vb >> 7, b = vb & 127;
    int tid = threadIdx.x;

    float cnt = (float)g_counts[b];
    if (cnt < 1.f) cnt = 1.f;
    sp[tid] = g_pool[(v * BB + b) * HH + tid] / cnt;
    __syncthreads();

    float acc = b2[tid];
    #pragma unroll 8
    for (int h = 0; h < HH; h++) acc += sp[h] * W2[h * HH + tid];
    sy[tid] = acc;
    __syncthreads();

    if (tid < CC) {
        float l = bcv[tid];
        #pragma unroll 8
        for (int h = 0; h < HH; h++) l += sy[h] * Wc[h * CC + tid];
        slog[tid] = l;
    }
    __syncthreads();

    if (tid == 0) {
        float mx = -1e30f;
        #pragma unroll
        for (int c = 0; c < CC; c++) mx = fmaxf(mx, slog[c]);
        float s = 0.f, e[CC];
        #pragma unroll
        for (int c = 0; c < CC; c++) { e[c] = expf(slog[c] - mx); s += e[c]; }
        float invs = 1.f / s;
        #pragma unroll
        for (int c = 0; c < CC; c++) g_probs[(v * BB + b) * CC + c] = e[c] * invs;
        if (v == 0) {
            #pragma unroll
            for (int c = 0; c < CC; c++) out[b * CC + c] = slog[c];
        }
    }
}

__global__ void k_loss(float* __restrict__ out, int out_size) {
    __shared__ float sc[BB], se[BB];
    int b = threadIdx.x;
    float mp[CC];
    #pragma unroll
    for (int c = 0; c < CC; c++) {
        float s = 0.f;
        #pragma unroll
        for (int v = 0; v < VV; v++) s += g_probs[(v * BB + b) * CC + c];
        mp[c] = s * (1.0f / VV);
    }
    float cons = 0.f;
    #pragma unroll
    for (int v = 0; v < VV; v++)
        #pragma unroll
        for (int c = 0; c < CC; c++) {
            float d = g_probs[(v * BB + b) * CC + c] - mp[c];
            cons += d * d;
        }
    float ent = 0.f;
    #pragma unroll
    for (int c = 0; c < CC; c++) ent -= mp[c] * logf(mp[c] + 1e-8f);
    sc[b] = cons; se[b] = ent;
    __syncthreads();
    for (int s = 64; s > 0; s >>= 1) {
        if (b < s) { sc[b] += sc[b + s]; se[b] += se[b + s]; }
        __syncthreads();
    }
    if (b == 0)
        out[out_size - 1] = 1.0f * (sc[0] / (float)(VV * BB)) + se[0] / (float)BB;
}

// ---------------------------------------------------------------------------
extern "C" void kernel_launch(void* const* d_in, const int* in_sizes, int n_in,
                              void* d_out, int out_size) {
    const float* x     = (const float*)d_in[0];
    const int*   ei    = (const int*)d_in[1];
    const int*   batch = (const int*)d_in[2];
    const float* dm    = (const float*)d_in[3];
    const float* masks = (const float*)d_in[4];
    const float* W1    = (const float*)d_in[5];
    const float* b1    = (const float*)d_in[6];
    const float* W2    = (const float*)d_in[7];
    const float* b2    = (const float*)d_in[8];
    const float* Wc    = (const float*)d_in[9];
    const float* bcv   = (const float*)d_in[10];
    float* out = (float*)d_out;

    k_zero  <<<(VV*BB*HH + 255) / 256, 256>>>();
    k_hist  <<<(EE + 255) / 256, 256>>>(ei);
    k_scan  <<<1, 1024>>>();
    k_fill  <<<(EE + 255) / 256, 256>>>(ei);
    k_counts<<<(NN + 255) / 256, 256>>>(batch);

    k_convA <<<(NPAD*HH/4 + 255) / 256, 256>>>(x, dm);
    k_convW <<<(HH*HH/4 + 255) / 256, 256>>>(W1);

    dim3 ggrid(HH / 64, NPAD / 128);
    k_gemm_wmma<<<ggrid, 256>>>();

    int wgrid = (NN * 32 + 255) / 256;
    k_step1<<<wgrid, 256>>>(masks);
    k_spmm4<<<wgrid, 256>>>(0);   // step 2: viewI -> tmpI
    k_spmm4<<<wgrid, 256>>>(1);   // step 3: tmpI -> viewI

    dim3 pgrid((NN + 63) / 64, VV);
    k_pool<<<pgrid, 256>>>(batch, b1);

    k_head<<<VV * BB, 256>>>(W2, b2, Wc, bcv, out);
    k_loss<<<1, BB>>>(out, out_size);
}

// round 7
// speedup vs baseline: 1.3882x; 1.0565x over previous
#include <cuda_runtime.h>
#include <cuda_fp16.h>
#include <mma.h>
using namespace nvcuda;

#define NN 50000
#define NPAD 50048            // 391 * 128, pad for wmma tiles
#define EE 800000
#define HH 256
#define BB 128
#define VV 4
#define CC 10
#define PH 512                // pair row width: 2 views * 256 feats

// ---- scratch (device globals; no allocation allowed) ----
__device__ int    g_degcnt[NN];
__device__ int    g_rowptr[NN+1];
__device__ int    g_fill[NN];
__device__ float  g_invdeg[NN];
__device__ int    g_col[EE];
__device__ int    g_counts[BB];
__device__ float4 g_mask4[NN];              // transposed node masks
__device__ __half g_xh[NPAD*HH];            // (x*dropout) fp16, zero-padded rows
__device__ __half g_w1h[HH*HH];             // W1 fp16
__device__ __half g_z[NPAD*HH];             // (x*dropout) @ W1, fp16
__device__ __half g_pairs[2][(size_t)NN*PH]; // view pairs {0,1},{2,3}: [node][v2][256]
__device__ __half g_ptmp[2][(size_t)NN*PH];  // ping-pong per pair
__device__ float  g_pool[VV*BB*HH];
__device__ float  g_probs[VV*BB*CC];

// ---------------------------------------------------------------------------
__global__ void k_zero() {
    int i = blockIdx.x * blockDim.x + threadIdx.x;
    if (i < NN) g_degcnt[i] = 0;
    if (i < BB) g_counts[i] = 0;
    if (i < VV*BB*HH) g_pool[i] = 0.f;
}

// histogram over edge rows + batch counts + mask transpose, one launch
__global__ void k_hist(const int* __restrict__ ei, const int* __restrict__ batch,
                       const float* __restrict__ masks) {
    int e = blockIdx.x * blockDim.x + threadIdx.x;
    if (e < EE) {
        int r = ei[e];
        if ((unsigned)r < NN) atomicAdd(&g_degcnt[r], 1);
    }
    if (e < NN) {
        int b = batch[e];
        if ((unsigned)b < BB) atomicAdd(&g_counts[b], 1);
        g_mask4[e] = make_float4(masks[e], masks[NN + e], masks[2*NN + e], masks[3*NN + e]);
    }
}

__global__ void k_scan() {
    __shared__ int part[1024];
    int tid = threadIdx.x;
    const int CH = (NN + 1023) / 1024;
    int lo = tid * CH;
    int hi = lo + CH; if (hi > NN) hi = NN;
    if (lo > NN) lo = NN;
    int s = 0;
    for (int i = lo; i < hi; i++) s += g_degcnt[i];
    part[tid] = s;
    __syncthreads();
    if (tid == 0) {
        int run = 0;
        for (int i = 0; i < 1024; i++) { int t = part[i]; part[i] = run; run += t; }
        g_rowptr[NN] = run;
    }
    __syncthreads();
    int run = part[tid];
    for (int i = lo; i < hi; i++) {
        int c = g_degcnt[i];
        g_rowptr[i] = run;
        g_fill[i]   = run;
        g_invdeg[i] = 1.0f / (float)(c + 1);
        run += c;
    }
}

__global__ void k_fill(const int* __restrict__ ei) {
    int e = blockIdx.x * blockDim.x + threadIdx.x;
    if (e < EE) {
        int r = ei[e];
        int c = ei[EE + e];
        if ((unsigned)r < NN && (unsigned)c < NN) {
            int p = atomicAdd(&g_fill[r], 1);
            if ((unsigned)p < EE) g_col[p] = c;
        }
    }
}

// ---------------------------------------------------------------------------
// fp32 -> fp16 conversions
__global__ void k_convA(const float* __restrict__ x, const float* __restrict__ dm) {
    int i = blockIdx.x * blockDim.x + threadIdx.x;
    int base = i * 4;
    if (base >= NPAD*HH) return;
    __half2 h[2];
    if (base < NN*HH) {
        float4 xv = *(const float4*)(x + base);
        float4 dv = *(const float4*)(dm + base);
        h[0] = __floats2half2_rn(xv.x*dv.x, xv.y*dv.y);
        h[1] = __floats2half2_rn(xv.z*dv.z, xv.w*dv.w);
    } else {
        h[0] = __floats2half2_rn(0.f, 0.f);
        h[1] = h[0];
    }
    *(uint2*)(g_xh + base) = *(uint2*)h;
}

__global__ void k_convW(const float* __restrict__ W1) {
    int i = blockIdx.x * blockDim.x + threadIdx.x;
    int base = i * 4;
    if (base >= HH*HH) return;
    float4 w = *(const float4*)(W1 + base);
    __half2 h[2];
    h[0] = __floats2half2_rn(w.x, w.y);
    h[1] = __floats2half2_rn(w.z, w.w);
    *(uint2*)(g_w1h + base) = *(uint2*)h;
}

// ---------------------------------------------------------------------------
// z = g_xh @ g_w1h via wmma fp16 (fp32 accum)
__global__ __launch_bounds__(256) void k_gemm_wmma() {
    __shared__ float stage[8][32][36];
    int warp = threadIdx.x >> 5;
    int lane = threadIdx.x & 31;
    int wm = warp >> 1, wn = warp & 1;
    int m0 = blockIdx.y * 128 + wm * 32;
    int n0 = blockIdx.x * 64 + wn * 32;

    wmma::fragment<wmma::accumulator, 16, 16, 16, float> c[2][2];
    #pragma unroll
    for (int i = 0; i < 2; i++)
        #pragma unroll
        for (int j = 0; j < 2; j++) wmma::fill_fragment(c[i][j], 0.f);

    for (int k = 0; k < HH; k += 16) {
        wmma::fragment<wmma::matrix_a, 16, 16, 16, __half, wmma::row_major> a[2];
        wmma::fragment<wmma::matrix_b, 16, 16, 16, __half, wmma::row_major> b[2];
        #pragma unroll
        for (int i = 0; i < 2; i++)
            wmma::load_matrix_sync(a[i], g_xh + (size_t)(m0 + 16*i) * HH + k, HH);
        #pragma unroll
        for (int j = 0; j < 2; j++)
            wmma::load_matrix_sync(b[j], g_w1h + (size_t)k * HH + n0 + 16*j, HH);
        #pragma unroll
        for (int i = 0; i < 2; i++)
            #pragma unroll
            for (int j = 0; j < 2; j++)
                wmma::mma_sync(c[i][j], a[i], b[j], c[i][j]);
    }

    #pragma unroll
    for (int i = 0; i < 2; i++)
        #pragma unroll
        for (int j = 0; j < 2; j++)
            wmma::store_matrix_sync(&stage[warp][16*i][16*j], c[i][j], 36, wmma::mem_row_major);
    __syncwarp();

    const float* srow = &stage[warp][lane][0];
    __half2 h[16];
    #pragma unroll
    for (int p = 0; p < 16; p++)
        h[p] = __floats2half2_rn(srow[2*p], srow[2*p+1]);
    __half* dst = g_z + (size_t)(m0 + lane) * HH + n0;
    #pragma unroll
    for (int p = 0; p < 4; p++)
        ((uint4*)dst)[p] = ((uint4*)h)[p];
}

// ---------------------------------------------------------------------------
__device__ __forceinline__ void load_row8(const __half* base, int lane, float f[8]) {
    uint4 raw = ((const uint4*)base)[lane];
    __half2* h = (__half2*)&raw;
    float2 t;
    t = __half22float2(h[0]); f[0] = t.x; f[1] = t.y;
    t = __half22float2(h[1]); f[2] = t.x; f[3] = t.y;
    t = __half22float2(h[2]); f[4] = t.x; f[5] = t.y;
    t = __half22float2(h[3]); f[6] = t.x; f[7] = t.y;
}
__device__ __forceinline__ void store_row8(__half* base, int lane, const float f[8], float scale) {
    __half2 h[4];
    #pragma unroll
    for (int p = 0; p < 4; p++)
        h[p] = __floats2half2_rn(f[2*p] * scale, f[2*p+1] * scale);
    ((uint4*)base)[lane] = *(uint4*)h;
}

// Fused first propagation step for all 4 views; writes pair layouts.
__global__ __launch_bounds__(256) void k_step1() {
    int gw = (blockIdx.x * blockDim.x + threadIdx.x) >> 5;
    int lane = threadIdx.x & 31;
    if (gw >= NN) return;
    int r = gw;

    float s[8];
    load_row8(g_z + (size_t)r * HH, lane, s);

    float4 mr = g_mask4[r];
    float mm[VV] = {mr.x, mr.y, mr.z, mr.w};
    float a[VV][8];
    #pragma unroll
    for (int v = 0; v < VV; v++)
        #pragma unroll
        for (int q = 0; q < 8; q++) a[v][q] = s[q] * mm[v];

    int jb = g_rowptr[r], je = g_rowptr[r + 1];
    for (int j = jb; j < je; j++) {
        int c = g_col[j];
        float cf[8];
        load_row8(g_z + (size_t)c * HH, lane, cf);
        float4 mc = g_mask4[c];
        float mv[VV] = {mc.x, mc.y, mc.z, mc.w};
        #pragma unroll
        for (int v = 0; v < VV; v++)
            #pragma unroll
            for (int q = 0; q < 8; q++) a[v][q] += mv[v] * cf[q];
    }
    float inv = g_invdeg[r];
    #pragma unroll
    for (int v = 0; v < VV; v++)
        store_row8(g_pairs[v >> 1] + (size_t)r * PH + (v & 1) * HH, lane, a[v], inv);
}

// one propagation step for one view-pair; dir=0: pairs->ptmp, dir=1: ptmp->pairs
__global__ __launch_bounds__(256) void k_spmm2(int pair, int dir) {
    const __half* in = dir ? g_ptmp[pair] : g_pairs[pair];
    __half* out      = dir ? g_pairs[pair] : g_ptmp[pair];

    int gw = (blockIdx.x * blockDim.x + threadIdx.x) >> 5;
    int lane = threadIdx.x & 31;
    if (gw >= NN) return;
    int r = gw;

    float a0[8], a1[8];
    const __half* srow = in + (size_t)r * PH;
    load_row8(srow,      lane, a0);   // self loop, view sub0
    load_row8(srow + HH, lane, a1);   // view sub1

    int jb = g_rowptr[r], je = g_rowptr[r + 1];
    int j = jb;
    for (; j + 1 < je; j += 2) {
        int c0 = g_col[j], c1 = g_col[j + 1];
        const __half* p0 = in + (size_t)c0 * PH;
        const __half* p1 = in + (size_t)c1 * PH;
        float u0[8], u1[8], w0[8], w1[8];
        load_row8(p0,      lane, u0);
        load_row8(p0 + HH, lane, u1);
        load_row8(p1,      lane, w0);
        load_row8(p1 + HH, lane, w1);
        #pragma unroll
        for (int q = 0; q < 8; q++) { a0[q] += u0[q] + w0[q]; a1[q] += u1[q] + w1[q]; }
    }
    if (j < je) {
        int c = g_col[j];
        const __half* p = in + (size_t)c * PH;
        float u0[8], u1[8];
        load_row8(p,      lane, u0);
        load_row8(p + HH, lane, u1);
        #pragma unroll
        for (int q = 0; q < 8; q++) { a0[q] += u0[q]; a1[q] += u1[q]; }
    }
    float inv = g_invdeg[r];
    __half* orow = out + (size_t)r * PH;
    store_row8(orow,      lane, a0, inv);
    store_row8(orow + HH, lane, a1, inv);
}

// ---------------------------------------------------------------------------
// pooled[v][b][f] += relu(state[r][v][f] + b1[f]) for batch[r]==b
__global__ __launch_bounds__(256) void k_pool(const int* __restrict__ batch,
                                              const float* __restrict__ b1) {
    int v  = blockIdx.y;
    int f  = threadIdx.x;
    int r0 = blockIdx.x * 64;
    const __half* in = g_pairs[v >> 1] + (size_t)(v & 1) * HH;
    float bias = b1[f];
    float acc = 0.f;
    int curb = -1;
    int rend = r0 + 64; if (rend > NN) rend = NN;
    for (int r = r0; r < rend; r++) {
        int b = batch[r];
        if ((unsigned)b >= BB) continue;
        if (b != curb) {
            if (curb >= 0) atomicAdd(&g_pool[(curb + v * BB) * HH + f], acc);
            acc = 0.f; curb = b;
        }
        float val = __half2float(in[(size_t)r * PH + f]) + bias;
        acc += fmaxf(val, 0.f);
    }
    if (curb >= 0) atomicAdd(&g_pool[(curb + v * BB) * HH + f], acc);
}

__global__ __launch_bounds__(256) void k_head(const float* __restrict__ W2,
                                              const float* __restrict__ b2,
                                              const float* __restrict__ Wc,
                                              const float* __restrict__ bcv,
                                              float* __restrict__ out) {
    __shared__ float sp[HH];
    __shared__ float sy[HH];
    __shared__ float slog[CC];
    int vb = blockIdx.x;
    int v = vb >> 7, b = vb & 127;
    int tid = threadIdx.x;

    float cnt = (float)g_counts[b];
    if (cnt < 1.f) cnt = 1.f;
    sp[tid] = g_pool[(v * BB + b) * HH + tid] / cnt;
    __syncthreads();

    float acc = b2[tid];
    #pragma unroll 8
    for (int h = 0; h < HH; h++) acc += sp[h] * W2[h * HH + tid];
    sy[tid] = acc;
    __syncthreads();

    if (tid < CC) {
        float l = bcv[tid];
        #pragma unroll 8
        for (int h = 0; h < HH; h++) l += sy[h] * Wc[h * CC + tid];
        slog[tid] = l;
    }
    __syncthreads();

    if (tid == 0) {
        float mx = -1e30f;
        #pragma unroll
        for (int c = 0; c < CC; c++) mx = fmaxf(mx, slog[c]);
        float s = 0.f, e[CC];
        #pragma unroll
        for (int c = 0; c < CC; c++) { e[c] = expf(slog[c] - mx); s += e[c]; }
        float invs = 1.f / s;
        #pragma unroll
        for (int c = 0; c < CC; c++) g_probs[(v * BB + b) * CC + c] = e[c] * invs;
        if (v == 0) {
            #pragma unroll
            for (int c = 0; c < CC; c++) out[b * CC + c] = slog[c];
        }
    }
}

__global__ void k_loss(float* __restrict__ out, int out_size) {
    __shared__ float sc[BB], se[BB];
    int b = threadIdx.x;
    float mp[CC];
    #pragma unroll
    for (int c = 0; c < CC; c++) {
        float s = 0.f;
        #pragma unroll
        for (int v = 0; v < VV; v++) s += g_probs[(v * BB + b) * CC + c];
        mp[c] = s * (1.0f / VV);
    }
    float cons = 0.f;
    #pragma unroll
    for (int v = 0; v < VV; v++)
        #pragma unroll
        for (int c = 0; c < CC; c++) {
            float d = g_probs[(v * BB + b) * CC + c] - mp[c];
            cons += d * d;
        }
    float ent = 0.f;
    #pragma unroll
    for (int c = 0; c < CC; c++) ent -= mp[c] * logf(mp[c] + 1e-8f);
    sc[b] = cons; se[b] = ent;
    __syncthreads();
    for (int s = 64; s > 0; s >>= 1) {
        if (b < s) { sc[b] += sc[b + s]; se[b] += se[b + s]; }
        __syncthreads();
    }
    if (b == 0)
        out[out_size - 1] = 1.0f * (sc[0] / (float)(VV * BB)) + se[0] / (float)BB;
}

// ---------------------------------------------------------------------------
extern "C" void kernel_launch(void* const* d_in, const int* in_sizes, int n_in,
                              void* d_out, int out_size) {
    const float* x     = (const float*)d_in[0];
    const int*   ei    = (const int*)d_in[1];
    const int*   batch = (const int*)d_in[2];
    const float* dm    = (const float*)d_in[3];
    const float* masks = (const float*)d_in[4];
    const float* W1    = (const float*)d_in[5];
    const float* b1    = (const float*)d_in[6];
    const float* W2    = (const float*)d_in[7];
    const float* b2    = (const float*)d_in[8];
    const float* Wc    = (const float*)d_in[9];
    const float* bcv   = (const float*)d_in[10];
    float* out = (float*)d_out;

    k_zero <<<(VV*BB*HH + 255) / 256, 256>>>();
    k_hist <<<(EE + 255) / 256, 256>>>(ei, batch, masks);
    k_scan <<<1, 1024>>>();
    k_fill <<<(EE + 255) / 256, 256>>>(ei);

    k_convA<<<(NPAD*HH/4 + 255) / 256, 256>>>(x, dm);
    k_convW<<<(HH*HH/4 + 255) / 256, 256>>>(W1);

    dim3 ggrid(HH / 64, NPAD / 128);
    k_gemm_wmma<<<ggrid, 256>>>();

    int wgrid = (NN * 32 + 255) / 256;
    k_step1<<<wgrid, 256>>>();
    k_spmm2<<<wgrid, 256>>>(0, 0);   // pair0 step2
    k_spmm2<<<wgrid, 256>>>(0, 1);   // pair0 step3
    k_spmm2<<<wgrid, 256>>>(1, 0);   // pair1 step2
    k_spmm2<<<wgrid, 256>>>(1, 1);   // pair1 step3

    dim3 pgrid((NN + 63) / 64, VV);
    k_pool<<<pgrid, 256>>>(batch, b1);

    k_head<<<VV * BB, 256>>>(W2, b2, Wc, bcv, out);
    k_loss<<<1, BB>>>(out, out_size);
}

// round 8
// speedup vs baseline: 1.5809x; 1.1388x over previous
#include <cuda_runtime.h>
#include <cuda_fp16.h>
#include <mma.h>
using namespace nvcuda;

#define NN 50000
#define NPAD 50048            // 782 * 64, pad for wmma tiles
#define EE 800000
#define HH 256
#define BB 128
#define VV 4
#define CC 10
#define PH 512                // pair row width: 2 views * 256 feats
#define KC 32                 // gemm k-chunk

// ---- scratch (device globals; no allocation allowed) ----
__device__ int    g_degcnt[NN];
__device__ int    g_rowptr[NN+1];
__device__ int    g_fill[NN];
__device__ float  g_invdeg[NN];
__device__ int    g_col[EE];
__device__ int    g_counts[BB];
__device__ float4 g_mask4[NN];              // transposed node masks
__device__ __half g_w1h[HH*HH];             // W1 fp16
__device__ __half g_z[NPAD*HH];             // (x*dropout) @ W1, fp16
__device__ __half g_pairs[2][(size_t)NN*PH]; // view pairs {0,1},{2,3}
__device__ __half g_ptmp[2][(size_t)NN*PH];  // ping-pong per pair
__device__ float  g_pool[VV*BB*HH];
__device__ float  g_probs[VV*BB*CC];

// ---------------------------------------------------------------------------
// zero counters + convert W1 to fp16 (no dependency between the two)
__global__ void k_zero(const float* __restrict__ W1) {
    int i = blockIdx.x * blockDim.x + threadIdx.x;
    if (i < NN) g_degcnt[i] = 0;
    if (i < BB) g_counts[i] = 0;
    if (i < VV*BB*HH) g_pool[i] = 0.f;
    if (i < HH*HH/4) {
        float4 w = *(const float4*)(W1 + i * 4);
        __half2 h[2];
        h[0] = __floats2half2_rn(w.x, w.y);
        h[1] = __floats2half2_rn(w.z, w.w);
        *(uint2*)(g_w1h + i * 4) = *(uint2*)h;
    }
}

// histogram over edge rows + batch counts + mask transpose, one launch
__global__ void k_hist(const int* __restrict__ ei, const int* __restrict__ batch,
                       const float* __restrict__ masks) {
    int e = blockIdx.x * blockDim.x + threadIdx.x;
    if (e < EE) {
        int r = ei[e];
        if ((unsigned)r < NN) atomicAdd(&g_degcnt[r], 1);
    }
    if (e < NN) {
        int b = batch[e];
        if ((unsigned)b < BB) atomicAdd(&g_counts[b], 1);
        g_mask4[e] = make_float4(masks[e], masks[NN + e], masks[2*NN + e], masks[3*NN + e]);
    }
}

// hierarchical scan: per-thread chunk sums -> warp shfl scan -> warp0 scan -> expand
__global__ void k_scan() {
    __shared__ int winc[32];   // per-warp inclusive totals
    __shared__ int woff[32];   // per-warp exclusive offsets
    int tid = threadIdx.x;
    int lane = tid & 31, wid = tid >> 5;
    const int CH = (NN + 1023) / 1024;   // 49
    int lo = tid * CH; if (lo > NN) lo = NN;
    int hi = lo + CH;  if (hi > NN) hi = NN;
    int s = 0;
    for (int i = lo; i < hi; i++) s += g_degcnt[i];
    // inclusive warp scan of s
    int inc = s;
    #pragma unroll
    for (int d = 1; d < 32; d <<= 1) {
        int t = __shfl_up_sync(0xffffffffu, inc, d);
        if (lane >= d) inc += t;
    }
    if (lane == 31) winc[wid] = inc;
    __syncthreads();
    if (wid == 0) {
        int v = winc[lane];
        int vi = v;
        #pragma unroll
        for (int d = 1; d < 32; d <<= 1) {
            int t = __shfl_up_sync(0xffffffffu, vi, d);
            if (lane >= d) vi += t;
        }
        woff[lane] = vi - v;     // exclusive
        if (lane == 31) winc[0] = vi;   // grand total (reuse slot 0 after sync)
    }
    __syncthreads();
    int run = woff[wid] + (inc - s);    // exclusive prefix for this thread
    for (int i = lo; i < hi; i++) {
        int c = g_degcnt[i];
        g_rowptr[i] = run;
        g_fill[i]   = run;
        g_invdeg[i] = 1.0f / (float)(c + 1);
        run += c;
    }
    if (tid == 0) g_rowptr[NN] = winc[0];
}

__global__ void k_fill(const int* __restrict__ ei) {
    int e = blockIdx.x * blockDim.x + threadIdx.x;
    if (e < EE) {
        int r = ei[e];
        int c = ei[EE + e];
        if ((unsigned)r < NN && (unsigned)c < NN) {
            int p = atomicAdd(&g_fill[r], 1);
            if ((unsigned)p < EE) g_col[p] = c;
        }
    }
}

// ---------------------------------------------------------------------------
// Fused dropout-multiply + fp16 convert + GEMM:  z = (x*dm) @ W1
// Block: 256 thr, tile M=64 N=256, K chunks of 32 staged in smem.
__global__ __launch_bounds__(256) void k_gemm_fused(const float* __restrict__ x,
                                                    const float* __restrict__ dm) {
    __shared__ __align__(16) __half As[64][KC + 8];    // 64 x 40 = 5120 B
    __shared__ __align__(16) __half Bs[KC][HH + 8];    // 32 x 264 = 16896 B
    int tid = threadIdx.x;
    int warp = tid >> 5, lane = tid & 31;
    int wm = warp >> 2;        // 0..1 : 32-row group
    int wn = warp & 3;         // 0..3 : 64-col group
    int m0 = blockIdx.x * 64;

    wmma::fragment<wmma::accumulator, 16, 16, 16, float> c[2][4];
    #pragma unroll
    for (int i = 0; i < 2; i++)
        #pragma unroll
        for (int j = 0; j < 4; j++) wmma::fill_fragment(c[i][j], 0.f);

    for (int kk = 0; kk < HH; kk += KC) {
        // stage A: 64 rows x 32 cols fp32*2 -> fp16  (512 float4 slots, 2/thread)
        #pragma unroll
        for (int i = 0; i < 2; i++) {
            int idx = tid + i * 256;          // 0..511
            int row = idx >> 3;               // 0..63
            int c4  = (idx & 7) * 4;          // 0..28
            int grow = m0 + row;
            __half2 h0, h1;
            if (grow < NN) {
                float4 xv = *(const float4*)(x  + (size_t)grow * HH + kk + c4);
                float4 dv = *(const float4*)(dm + (size_t)grow * HH + kk + c4);
                h0 = __floats2half2_rn(xv.x*dv.x, xv.y*dv.y);
                h1 = __floats2half2_rn(xv.z*dv.z, xv.w*dv.w);
            } else {
                h0 = __floats2half2_rn(0.f, 0.f);
                h1 = h0;
            }
            *(__half2*)&As[row][c4]     = h0;
            *(__half2*)&As[row][c4 + 2] = h1;
        }
        // stage B: 32 x 256 halves (1024 uint4 slots, 4/thread)
        #pragma unroll
        for (int i = 0; i < 4; i++) {
            int idx = tid + i * 256;          // 0..1023
            int row = idx >> 5;               // 0..31
            int c8  = (idx & 31) * 8;         // 0..248
            *(uint4*)&Bs[row][c8] = *(const uint4*)(g_w1h + (size_t)(kk + row) * HH + c8);
        }
        __syncthreads();
        #pragma unroll
        for (int ks = 0; ks < KC; ks += 16) {
            wmma::fragment<wmma::matrix_a, 16, 16, 16, __half, wmma::row_major> a[2];
            #pragma unroll
            for (int i = 0; i < 2; i++)
                wmma::load_matrix_sync(a[i], &As[wm*32 + 16*i][ks], KC + 8);
            #pragma unroll
            for (int j = 0; j < 4; j++) {
                wmma::fragment<wmma::matrix_b, 16, 16, 16, __half, wmma::row_major> b;
                wmma::load_matrix_sync(b, &Bs[ks][wn*64 + 16*j], HH + 8);
                wmma::mma_sync(c[0][j], a[0], b, c[0][j]);
                wmma::mma_sync(c[1][j], a[1], b, c[1][j]);
            }
        }
        __syncthreads();
    }

    // epilogue: stage each 16x16 frag through smem (reuse Bs), convert to fp16
    float* stg = (float*)Bs + warp * 320;    // 16x20 floats per warp
    #pragma unroll
    for (int i = 0; i < 2; i++)
        #pragma unroll
        for (int j = 0; j < 4; j++) {
            wmma::store_matrix_sync(stg, c[i][j], 20, wmma::mem_row_major);
            __syncwarp();
            if (lane < 16) {
                const float* sr = stg + lane * 20;
                __half2 hh[8];
                #pragma unroll
                for (int p = 0; p < 8; p++)
                    hh[p] = __floats2half2_rn(sr[2*p], sr[2*p+1]);
                int gr = m0 + wm*32 + i*16 + lane;
                __half* dst = g_z + (size_t)gr * HH + wn*64 + j*16;
                ((uint4*)dst)[0] = ((uint4*)hh)[0];
                ((uint4*)dst)[1] = ((uint4*)hh)[1];
            }
            __syncwarp();
        }
}

// ---------------------------------------------------------------------------
__device__ __forceinline__ void load_row8(const __half* base, int lane, float f[8]) {
    uint4 raw = ((const uint4*)base)[lane];
    __half2* h = (__half2*)&raw;
    float2 t;
    t = __half22float2(h[0]); f[0] = t.x; f[1] = t.y;
    t = __half22float2(h[1]); f[2] = t.x; f[3] = t.y;
    t = __half22float2(h[2]); f[4] = t.x; f[5] = t.y;
    t = __half22float2(h[3]); f[6] = t.x; f[7] = t.y;
}
__device__ __forceinline__ void store_row8(__half* base, int lane, const float f[8], float scale) {
    __half2 h[4];
    #pragma unroll
    for (int p = 0; p < 4; p++)
        h[p] = __floats2half2_rn(f[2*p] * scale, f[2*p+1] * scale);
    ((uint4*)base)[lane] = *(uint4*)h;
}

// Fused first propagation step for all 4 views; writes pair layouts.
__global__ __launch_bounds__(256) void k_step1() {
    int gw = (blockIdx.x * blockDim.x + threadIdx.x) >> 5;
    int lane = threadIdx.x & 31;
    if (gw >= NN) return;
    int r = gw;

    float s[8];
    load_row8(g_z + (size_t)r * HH, lane, s);

    float4 mr = g_mask4[r];
    float mm[VV] = {mr.x, mr.y, mr.z, mr.w};
    float a[VV][8];
    #pragma unroll
    for (int v = 0; v < VV; v++)
        #pragma unroll
        for (int q = 0; q < 8; q++) a[v][q] = s[q] * mm[v];

    int jb = g_rowptr[r], je = g_rowptr[r + 1];
    for (int j = jb; j < je; j++) {
        int c = g_col[j];
        float cf[8];
        load_row8(g_z + (size_t)c * HH, lane, cf);
        float4 mc = g_mask4[c];
        float mv[VV] = {mc.x, mc.y, mc.z, mc.w};
        #pragma unroll
        for (int v = 0; v < VV; v++)
            #pragma unroll
            for (int q = 0; q < 8; q++) a[v][q] += mv[v] * cf[q];
    }
    float inv = g_invdeg[r];
    #pragma unroll
    for (int v = 0; v < VV; v++)
        store_row8(g_pairs[v >> 1] + (size_t)r * PH + (v & 1) * HH, lane, a[v], inv);
}

// one propagation step for one view-pair; dir=0: pairs->ptmp, dir=1: ptmp->pairs
__global__ __launch_bounds__(256) void k_spmm2(int pair, int dir) {
    const __half* in = dir ? g_ptmp[pair] : g_pairs[pair];
    __half* out      = dir ? g_pairs[pair] : g_ptmp[pair];

    int gw = (blockIdx.x * blockDim.x + threadIdx.x) >> 5;
    int lane = threadIdx.x & 31;
    if (gw >= NN) return;
    int r = gw;

    float a0[8], a1[8];
    const __half* srow = in + (size_t)r * PH;
    load_row8(srow,      lane, a0);   // self loop, view sub0
    load_row8(srow + HH, lane, a1);   // view sub1

    int jb = g_rowptr[r], je = g_rowptr[r + 1];
    int j = jb;
    for (; j + 1 < je; j += 2) {
        int c0 = g_col[j], c1 = g_col[j + 1];
        const __half* p0 = in + (size_t)c0 * PH;
        const __half* p1 = in + (size_t)c1 * PH;
        float u0[8], u1[8], w0[8], w1[8];
        load_row8(p0,      lane, u0);
        load_row8(p0 + HH, lane, u1);
        load_row8(p1,      lane, w0);
        load_row8(p1 + HH, lane, w1);
        #pragma unroll
        for (int q = 0; q < 8; q++) { a0[q] += u0[q] + w0[q]; a1[q] += u1[q] + w1[q]; }
    }
    if (j < je) {
        int c = g_col[j];
        const __half* p = in + (size_t)c * PH;
        float u0[8], u1[8];
        load_row8(p,      lane, u0);
        load_row8(p + HH, lane, u1);
        #pragma unroll
        for (int q = 0; q < 8; q++) { a0[q] += u0[q]; a1[q] += u1[q]; }
    }
    float inv = g_invdeg[r];
    __half* orow = out + (size_t)r * PH;
    store_row8(orow,      lane, a0, inv);
    store_row8(orow + HH, lane, a1, inv);
}

// ---------------------------------------------------------------------------
// pooled[v][b][f] += relu(state[r][v][f] + b1[f]) for batch[r]==b
__global__ __launch_bounds__(256) void k_pool(const int* __restrict__ batch,
                                              const float* __restrict__ b1) {
    int v  = blockIdx.y;
    int f  = threadIdx.x;
    int r0 = blockIdx.x * 64;
    const __half* in = g_pairs[v >> 1] + (size_t)(v & 1) * HH;
    float bias = b1[f];
    float acc = 0.f;
    int curb = -1;
    int rend = r0 + 64; if (rend > NN) rend = NN;
    for (int r = r0; r < rend; r++) {
        int b = batch[r];
        if ((unsigned)b >= BB) continue;
        if (b != curb) {
            if (curb >= 0) atomicAdd(&g_pool[(curb + v * BB) * HH + f], acc);
            acc = 0.f; curb = b;
        }
        float val = __half2float(in[(size_t)r * PH + f]) + bias;
        acc += fmaxf(val, 0.f);
    }
    if (curb >= 0) atomicAdd(&g_pool[(curb + v * BB) * HH + f], acc);
}

__global__ __launch_bounds__(256) void k_head(const float* __restrict__ W2,
                                              const float* __restrict__ b2,
                                              const float* __restrict__ Wc,
                                              const float* __restrict__ bcv,
                                              float* __restrict__ out) {
    __shared__ float sp[HH];
    __shared__ float sy[HH];
    __shared__ float slog[CC];
    int vb = blockIdx.x;
    int v = vb >> 7, b = vb & 127;
    int tid = threadIdx.x;

    float cnt = (float)g_counts[b];
    if (cnt < 1.f) cnt = 1.f;
    sp[tid] = g_pool[(v * BB + b) * HH + tid] / cnt;
    __syncthreads();

    float acc = b2[tid];
    #pragma unroll 8
    for (int h = 0; h < HH; h++) acc += sp[h] * W2[h * HH + tid];
    sy[tid] = acc;
    __syncthreads();

    if (tid < CC) {
        float l = bcv[tid];
        #pragma unroll 8
        for (int h = 0; h < HH; h++) l += sy[h] * Wc[h * CC + tid];
        slog[tid] = l;
    }
    __syncthreads();

    if (tid == 0) {
        float mx = -1e30f;
        #pragma unroll
        for (int c = 0; c < CC; c++) mx = fmaxf(mx, slog[c]);
        float s = 0.f, e[CC];
        #pragma unroll
        for (int c = 0; c < CC; c++) { e[c] = expf(slog[c] - mx); s += e[c]; }
        float invs = 1.f / s;
        #pragma unroll
        for (int c = 0; c < CC; c++) g_probs[(v * BB + b) * CC + c] = e[c] * invs;
        if (v == 0) {
            #pragma unroll
            for (int c = 0; c < CC; c++) out[b * CC + c] = slog[c];
        }
    }
}

__global__ void k_loss(float* __restrict__ out, int out_size) {
    __shared__ float sc[BB], se[BB];
    int b = threadIdx.x;
    float mp[CC];
    #pragma unroll
    for (int c = 0; c < CC; c++) {
        float s = 0.f;
        #pragma unroll
        for (int v = 0; v < VV; v++) s += g_probs[(v * BB + b) * CC + c];
        mp[c] = s * (1.0f / VV);
    }
    float cons = 0.f;
    #pragma unroll
    for (int v = 0; v < VV; v++)
        #pragma unroll
        for (int c = 0; c < CC; c++) {
            float d = g_probs[(v * BB + b) * CC + c] - mp[c];
            cons += d * d;
        }
    float ent = 0.f;
    #pragma unroll
    for (int c = 0; c < CC; c++) ent -= mp[c] * logf(mp[c] + 1e-8f);
    sc[b] = cons; se[b] = ent;
    __syncthreads();
    for (int s = 64; s > 0; s >>= 1) {
        if (b < s) { sc[b] += sc[b + s]; se[b] += se[b + s]; }
        __syncthreads();
    }
    if (b == 0)
        out[out_size - 1] = 1.0f * (sc[0] / (float)(VV * BB)) + se[0] / (float)BB;
}

// ---------------------------------------------------------------------------
extern "C" void kernel_launch(void* const* d_in, const int* in_sizes, int n_in,
                              void* d_out, int out_size) {
    const float* x     = (const float*)d_in[0];
    const int*   ei    = (const int*)d_in[1];
    const int*   batch = (const int*)d_in[2];
    const float* dm    = (const float*)d_in[3];
    const float* masks = (const float*)d_in[4];
    const float* W1    = (const float*)d_in[5];
    const float* b1    = (const float*)d_in[6];
    const float* W2    = (const float*)d_in[7];
    const float* b2    = (const float*)d_in[8];
    const float* Wc    = (const float*)d_in[9];
    const float* bcv   = (const float*)d_in[10];
    float* out = (float*)d_out;

    k_zero<<<(VV*BB*HH + 255) / 256, 256>>>(W1);
    k_hist<<<(EE + 255) / 256, 256>>>(ei, batch, masks);
    k_scan<<<1, 1024>>>();
    k_fill<<<(EE + 255) / 256, 256>>>(ei);

    k_gemm_fused<<<NPAD / 64, 256>>>(x, dm);

    int wgrid = (NN * 32 + 255) / 256;
    k_step1<<<wgrid, 256>>>();
    k_spmm2<<<wgrid, 256>>>(0, 0);   // pair0 step2
    k_spmm2<<<wgrid, 256>>>(0, 1);   // pair0 step3
    k_spmm2<<<wgrid, 256>>>(1, 0);   // pair1 step2
    k_spmm2<<<wgrid, 256>>>(1, 1);   // pair1 step3

    dim3 pgrid((NN + 63) / 64, VV);
    k_pool<<<pgrid, 256>>>(batch, b1);

    k_head<<<VV * BB, 256>>>(W2, b2, Wc, bcv, out);
    k_loss<<<1, BB>>>(out, out_size);
}

// round 9
// speedup vs baseline: 1.6285x; 1.0301x over previous
#include <cuda_runtime.h>
#include <cuda_fp16.h>
#include <mma.h>
using namespace nvcuda;

#define NN 50000
#define NPAD 50048            // 782 * 64, pad for wmma tiles
#define EE 800000
#define HH 256
#define BB 128
#define VV 4
#define CC 10
#define PH 512                // pair row width: 2 views * 256 feats
#define KC 32                 // gemm k-chunk

// ---- scratch (device globals; no allocation allowed) ----
__device__ int    g_degcnt[NN];
__device__ int    g_rowptr[NN+1];
__device__ int    g_fill[NN];
__device__ float  g_invdeg[NN];
__device__ int    g_col[EE];
__device__ int    g_counts[BB];
__device__ float4 g_mask4[NN];              // transposed node masks
__device__ __half g_w1h[HH*HH];             // W1 fp16
__device__ __half g_z[NPAD*HH];             // (x*dropout) @ W1, fp16
__device__ __half g_pairs[2][(size_t)NN*PH]; // view pairs {0,1},{2,3}
__device__ __half g_ptmp[2][(size_t)NN*PH];  // ping-pong per pair
__device__ float  g_pool[VV*BB*HH];
__device__ float  g_probs[VV*BB*CC];

// ---------------------------------------------------------------------------
// zero counters + convert W1 to fp16 (no dependency between the two)
__global__ void k_zero(const float* __restrict__ W1) {
    int i = blockIdx.x * blockDim.x + threadIdx.x;
    if (i < NN) g_degcnt[i] = 0;
    if (i < BB) g_counts[i] = 0;
    if (i < VV*BB*HH) g_pool[i] = 0.f;
    if (i < HH*HH/4) {
        float4 w = *(const float4*)(W1 + i * 4);
        __half2 h[2];
        h[0] = __floats2half2_rn(w.x, w.y);
        h[1] = __floats2half2_rn(w.z, w.w);
        *(uint2*)(g_w1h + i * 4) = *(uint2*)h;
    }
}

// histogram over edge rows + batch counts + mask transpose, one launch
__global__ void k_hist(const int* __restrict__ ei, const int* __restrict__ batch,
                       const float* __restrict__ masks) {
    int e = blockIdx.x * blockDim.x + threadIdx.x;
    if (e < EE) {
        int r = ei[e];
        if ((unsigned)r < NN) atomicAdd(&g_degcnt[r], 1);
    }
    if (e < NN) {
        int b = batch[e];
        if ((unsigned)b < BB) atomicAdd(&g_counts[b], 1);
        g_mask4[e] = make_float4(masks[e], masks[NN + e], masks[2*NN + e], masks[3*NN + e]);
    }
}

// hierarchical scan: per-thread chunk sums -> warp shfl scan -> warp0 scan -> expand
__global__ void k_scan() {
    __shared__ int winc[32];
    __shared__ int woff[32];
    int tid = threadIdx.x;
    int lane = tid & 31, wid = tid >> 5;
    const int CH = (NN + 1023) / 1024;   // 49
    int lo = tid * CH; if (lo > NN) lo = NN;
    int hi = lo + CH;  if (hi > NN) hi = NN;
    int s = 0;
    for (int i = lo; i < hi; i++) s += g_degcnt[i];
    int inc = s;
    #pragma unroll
    for (int d = 1; d < 32; d <<= 1) {
        int t = __shfl_up_sync(0xffffffffu, inc, d);
        if (lane >= d) inc += t;
    }
    if (lane == 31) winc[wid] = inc;
    __syncthreads();
    if (wid == 0) {
        int v = winc[lane];
        int vi = v;
        #pragma unroll
        for (int d = 1; d < 32; d <<= 1) {
            int t = __shfl_up_sync(0xffffffffu, vi, d);
            if (lane >= d) vi += t;
        }
        woff[lane] = vi - v;
        if (lane == 31) winc[0] = vi;
    }
    __syncthreads();
    int run = woff[wid] + (inc - s);
    for (int i = lo; i < hi; i++) {
        int c = g_degcnt[i];
        g_rowptr[i] = run;
        g_fill[i]   = run;
        g_invdeg[i] = 1.0f / (float)(c + 1);
        run += c;
    }
    if (tid == 0) g_rowptr[NN] = winc[0];
}

__global__ void k_fill(const int* __restrict__ ei) {
    int e = blockIdx.x * blockDim.x + threadIdx.x;
    if (e < EE) {
        int r = ei[e];
        int c = ei[EE + e];
        if ((unsigned)r < NN && (unsigned)c < NN) {
            int p = atomicAdd(&g_fill[r], 1);
            if ((unsigned)p < EE) g_col[p] = c;
        }
    }
}

// ---------------------------------------------------------------------------
// Fused dropout-multiply + fp16 convert + GEMM:  z = (x*dm) @ W1
__global__ __launch_bounds__(256) void k_gemm_fused(const float* __restrict__ x,
                                                    const float* __restrict__ dm) {
    __shared__ __align__(16) __half As[64][KC + 8];
    __shared__ __align__(16) __half Bs[KC][HH + 8];
    int tid = threadIdx.x;
    int warp = tid >> 5, lane = tid & 31;
    int wm = warp >> 2;
    int wn = warp & 3;
    int m0 = blockIdx.x * 64;

    wmma::fragment<wmma::accumulator, 16, 16, 16, float> c[2][4];
    #pragma unroll
    for (int i = 0; i < 2; i++)
        #pragma unroll
        for (int j = 0; j < 4; j++) wmma::fill_fragment(c[i][j], 0.f);

    for (int kk = 0; kk < HH; kk += KC) {
        #pragma unroll
        for (int i = 0; i < 2; i++) {
            int idx = tid + i * 256;
            int row = idx >> 3;
            int c4  = (idx & 7) * 4;
            int grow = m0 + row;
            __half2 h0, h1;
            if (grow < NN) {
                float4 xv = *(const float4*)(x  + (size_t)grow * HH + kk + c4);
                float4 dv = *(const float4*)(dm + (size_t)grow * HH + kk + c4);
                h0 = __floats2half2_rn(xv.x*dv.x, xv.y*dv.y);
                h1 = __floats2half2_rn(xv.z*dv.z, xv.w*dv.w);
            } else {
                h0 = __floats2half2_rn(0.f, 0.f);
                h1 = h0;
            }
            *(__half2*)&As[row][c4]     = h0;
            *(__half2*)&As[row][c4 + 2] = h1;
        }
        #pragma unroll
        for (int i = 0; i < 4; i++) {
            int idx = tid + i * 256;
            int row = idx >> 5;
            int c8  = (idx & 31) * 8;
            *(uint4*)&Bs[row][c8] = *(const uint4*)(g_w1h + (size_t)(kk + row) * HH + c8);
        }
        __syncthreads();
        #pragma unroll
        for (int ks = 0; ks < KC; ks += 16) {
            wmma::fragment<wmma::matrix_a, 16, 16, 16, __half, wmma::row_major> a[2];
            #pragma unroll
            for (int i = 0; i < 2; i++)
                wmma::load_matrix_sync(a[i], &As[wm*32 + 16*i][ks], KC + 8);
            #pragma unroll
            for (int j = 0; j < 4; j++) {
                wmma::fragment<wmma::matrix_b, 16, 16, 16, __half, wmma::row_major> b;
                wmma::load_matrix_sync(b, &Bs[ks][wn*64 + 16*j], HH + 8);
                wmma::mma_sync(c[0][j], a[0], b, c[0][j]);
                wmma::mma_sync(c[1][j], a[1], b, c[1][j]);
            }
        }
        __syncthreads();
    }

    float* stg = (float*)Bs + warp * 320;
    #pragma unroll
    for (int i = 0; i < 2; i++)
        #pragma unroll
        for (int j = 0; j < 4; j++) {
            wmma::store_matrix_sync(stg, c[i][j], 20, wmma::mem_row_major);
            __syncwarp();
            if (lane < 16) {
                const float* sr = stg + lane * 20;
                __half2 hh[8];
                #pragma unroll
                for (int p = 0; p < 8; p++)
                    hh[p] = __floats2half2_rn(sr[2*p], sr[2*p+1]);
                int gr = m0 + wm*32 + i*16 + lane;
                __half* dst = g_z + (size_t)gr * HH + wn*64 + j*16;
                ((uint4*)dst)[0] = ((uint4*)hh)[0];
                ((uint4*)dst)[1] = ((uint4*)hh)[1];
            }
            __syncwarp();
        }
}

// ---------------------------------------------------------------------------
__device__ __forceinline__ void load_row8(const __half* base, int lane, float f[8]) {
    uint4 raw = ((const uint4*)base)[lane];
    __half2* h = (__half2*)&raw;
    float2 t;
    t = __half22float2(h[0]); f[0] = t.x; f[1] = t.y;
    t = __half22float2(h[1]); f[2] = t.x; f[3] = t.y;
    t = __half22float2(h[2]); f[4] = t.x; f[5] = t.y;
    t = __half22float2(h[3]); f[6] = t.x; f[7] = t.y;
}
// evict-first store: output rows are not re-read within the pass; keep the
// gather source resident in L2 instead.
__device__ __forceinline__ void store_row8_cs(__half* base, int lane, const float f[8], float scale) {
    __half2 h[4];
    #pragma unroll
    for (int p = 0; p < 4; p++)
        h[p] = __floats2half2_rn(f[2*p] * scale, f[2*p+1] * scale);
    __stcs((uint4*)base + lane, *(uint4*)h);
}

// Fused first propagation step for all 4 views; writes pair layouts.
__global__ __launch_bounds__(256) void k_step1() {
    int gw = (blockIdx.x * blockDim.x + threadIdx.x) >> 5;
    int lane = threadIdx.x & 31;
    if (gw >= NN) return;
    int r = gw;

    float s[8];
    load_row8(g_z + (size_t)r * HH, lane, s);

    float4 mr = g_mask4[r];
    float mm[VV] = {mr.x, mr.y, mr.z, mr.w};
    float a[VV][8];
    #pragma unroll
    for (int v = 0; v < VV; v++)
        #pragma unroll
        for (int q = 0; q < 8; q++) a[v][q] = s[q] * mm[v];

    int jb = g_rowptr[r], je = g_rowptr[r + 1];
    for (int j = jb; j < je; j++) {
        int c = g_col[j];
        float cf[8];
        load_row8(g_z + (size_t)c * HH, lane, cf);
        float4 mc = g_mask4[c];
        float mv[VV] = {mc.x, mc.y, mc.z, mc.w};
        #pragma unroll
        for (int v = 0; v < VV; v++)
            #pragma unroll
            for (int q = 0; q < 8; q++) a[v][q] += mv[v] * cf[q];
    }
    float inv = g_invdeg[r];
    #pragma unroll
    for (int v = 0; v < VV; v++)
        store_row8_cs(g_pairs[v >> 1] + (size_t)r * PH + (v & 1) * HH, lane, a[v], inv);
}

// one propagation step for one view-pair; dir=0: pairs->ptmp, dir=1: ptmp->pairs
__global__ __launch_bounds__(256) void k_spmm2(int pair, int dir) {
    const __half* in = dir ? g_ptmp[pair] : g_pairs[pair];
    __half* out      = dir ? g_pairs[pair] : g_ptmp[pair];

    int gw = (blockIdx.x * blockDim.x + threadIdx.x) >> 5;
    int lane = threadIdx.x & 31;
    if (gw >= NN) return;
    int r = gw;

    float a0[8], a1[8];
    const __half* srow = in + (size_t)r * PH;
    load_row8(srow,      lane, a0);
    load_row8(srow + HH, lane, a1);

    int jb = g_rowptr[r], je = g_rowptr[r + 1];
    int j = jb;
    for (; j + 1 < je; j += 2) {
        int c0 = g_col[j], c1 = g_col[j + 1];
        const __half* p0 = in + (size_t)c0 * PH;
        const __half* p1 = in + (size_t)c1 * PH;
        float u0[8], u1[8], w0[8], w1[8];
        load_row8(p0,      lane, u0);
        load_row8(p0 + HH, lane, u1);
        load_row8(p1,      lane, w0);
        load_row8(p1 + HH, lane, w1);
        #pragma unroll
        for (int q = 0; q < 8; q++) { a0[q] += u0[q] + w0[q]; a1[q] += u1[q] + w1[q]; }
    }
    if (j < je) {
        int c = g_col[j];
        const __half* p = in + (size_t)c * PH;
        float u0[8], u1[8];
        load_row8(p,      lane, u0);
        load_row8(p + HH, lane, u1);
        #pragma unroll
        for (int q = 0; q < 8; q++) { a0[q] += u0[q]; a1[q] += u1[q]; }
    }
    float inv = g_invdeg[r];
    __half* orow = out + (size_t)r * PH;
    store_row8_cs(orow,      lane, a0, inv);
    store_row8_cs(orow + HH, lane, a1, inv);
}

// ---------------------------------------------------------------------------
// pooled[v][b][f] += relu(state[r][v][f] + b1[f]) for batch[r]==b
__global__ __launch_bounds__(256) void k_pool(const int* __restrict__ batch,
                                              const float* __restrict__ b1) {
    int v  = blockIdx.y;
    int f  = threadIdx.x;
    int r0 = blockIdx.x * 64;
    const __half* in = g_pairs[v >> 1] + (size_t)(v & 1) * HH;
    float bias = b1[f];
    float acc = 0.f;
    int curb = -1;
    int rend = r0 + 64; if (rend > NN) rend = NN;
    for (int r = r0; r < rend; r++) {
        int b = batch[r];
        if ((unsigned)b >= BB) continue;
        if (b != curb) {
            if (curb >= 0) atomicAdd(&g_pool[(curb + v * BB) * HH + f], acc);
            acc = 0.f; curb = b;
        }
        float val = __half2float(in[(size_t)r * PH + f]) + bias;
        acc += fmaxf(val, 0.f);
    }
    if (curb >= 0) atomicAdd(&g_pool[(curb + v * BB) * HH + f], acc);
}

__global__ __launch_bounds__(256) void k_head(const float* __restrict__ W2,
                                              const float* __restrict__ b2,
                                              const float* __restrict__ Wc,
                                              const float* __restrict__ bcv,
                                              float* __restrict__ out) {
    __shared__ float sp[HH];
    __shared__ float sy[HH];
    __shared__ float slog[CC];
    int vb = blockIdx.x;
    int v = vb >> 7, b = vb & 127;
    int tid = threadIdx.x;

    float cnt = (float)g_counts[b];
    if (cnt < 1.f) cnt = 1.f;
    sp[tid] = g_pool[(v * BB + b) * HH + tid] / cnt;
    __syncthreads();

    float acc = b2[tid];
    #pragma unroll 8
    for (int h = 0; h < HH; h++) acc += sp[h] * W2[h * HH + tid];
    sy[tid] = acc;
    __syncthreads();

    if (tid < CC) {
        float l = bcv[tid];
        #pragma unroll 8
        for (int h = 0; h < HH; h++) l += sy[h] * Wc[h * CC + tid];
        slog[tid] = l;
    }
    __syncthreads();

    if (tid == 0) {
        float mx = -1e30f;
        #pragma unroll
        for (int c = 0; c < CC; c++) mx = fmaxf(mx, slog[c]);
        float s = 0.f, e[CC];
        #pragma unroll
        for (int c = 0; c < CC; c++) { e[c] = expf(slog[c] - mx); s += e[c]; }
        float invs = 1.f / s;
        #pragma unroll
        for (int c = 0; c < CC; c++) g_probs[(v * BB + b) * CC + c] = e[c] * invs;
        if (v == 0) {
            #pragma unroll
            for (int c = 0; c < CC; c++) out[b * CC + c] = slog[c];
        }
    }
}

__global__ void k_loss(float* __restrict__ out, int out_size) {
    __shared__ float sc[BB], se[BB];
    int b = threadIdx.x;
    float mp[CC];
    #pragma unroll
    for (int c = 0; c < CC; c++) {
        float s = 0.f;
        #pragma unroll
        for (int v = 0; v < VV; v++) s += g_probs[(v * BB + b) * CC + c];
        mp[c] = s * (1.0f / VV);
    }
    float cons = 0.f;
    #pragma unroll
    for (int v = 0; v < VV; v++)
        #pragma unroll
        for (int c = 0; c < CC; c++) {
            float d = g_probs[(v * BB + b) * CC + c] - mp[c];
            cons += d * d;
        }
    float ent = 0.f;
    #pragma unroll
    for (int c = 0; c < CC; c++) ent -= mp[c] * logf(mp[c] + 1e-8f);
    sc[b] = cons; se[b] = ent;
    __syncthreads();
    for (int s = 64; s > 0; s >>= 1) {
        if (b < s) { sc[b] += sc[b + s]; se[b] += se[b + s]; }
        __syncthreads();
    }
    if (b == 0)
        out[out_size - 1] = 1.0f * (sc[0] / (float)(VV * BB)) + se[0] / (float)BB;
}

// ---------------------------------------------------------------------------
extern "C" void kernel_launch(void* const* d_in, const int* in_sizes, int n_in,
                              void* d_out, int out_size) {
    const float* x     = (const float*)d_in[0];
    const int*   ei    = (const int*)d_in[1];
    const int*   batch = (const int*)d_in[2];
    const float* dm    = (const float*)d_in[3];
    const float* masks = (const float*)d_in[4];
    const float* W1    = (const float*)d_in[5];
    const float* b1    = (const float*)d_in[6];
    const float* W2    = (const float*)d_in[7];
    const float* b2    = (const float*)d_in[8];
    const float* Wc    = (const float*)d_in[9];
    const float* bcv   = (const float*)d_in[10];
    float* out = (float*)d_out;

    // fork/join: CSR chain on the capture (default) stream, GEMM on a side
    // stream. Streams/events are host objects (no device allocation) and the
    // fork/join event pattern is graph-capture-legal. Leaked intentionally:
    // destroying them before the harness ends capture would invalidate it.
    cudaStream_t s2;
    cudaStreamCreate(&s2);
    cudaEvent_t eFork, eJoin;
    cudaEventCreateWithFlags(&eFork, cudaEventDisableTiming);
    cudaEventCreateWithFlags(&eJoin, cudaEventDisableTiming);

    k_zero<<<(VV*BB*HH + 255) / 256, 256>>>(W1);
    cudaEventRecord(eFork, 0);
    cudaStreamWaitEvent(s2, eFork, 0);

    k_gemm_fused<<<NPAD / 64, 256, 0, s2>>>(x, dm);   // side stream
    cudaEventRecord(eJoin, s2);

    k_hist<<<(EE + 255) / 256, 256>>>(ei, batch, masks);
    k_scan<<<1, 1024>>>();
    k_fill<<<(EE + 255) / 256, 256>>>(ei);

    cudaStreamWaitEvent(0, eJoin, 0);                 // join before step1

    int wgrid = (NN * 32 + 255) / 256;
    k_step1<<<wgrid, 256>>>();
    k_spmm2<<<wgrid, 256>>>(0, 0);   // pair0 step2
    k_spmm2<<<wgrid, 256>>>(0, 1);   // pair0 step3
    k_spmm2<<<wgrid, 256>>>(1, 0);   // pair1 step2
    k_spmm2<<<wgrid, 256>>>(1, 1);   // pair1 step3

    dim3 pgrid((NN + 63) / 64, VV);
    k_pool<<<pgrid, 256>>>(batch, b1);

    k_head<<<VV * BB, 256>>>(W2, b2, Wc, bcv, out);
    k_loss<<<1, BB>>>(out, out_size);
}

// round 10
// speedup vs baseline: 1.9454x; 1.1946x over previous
#include <cuda_runtime.h>
#include <cuda_fp16.h>
#include <mma.h>
using namespace nvcuda;

#define NN 50000
#define NPAD 50048            // 782 * 64, pad for wmma tiles
#define EE 800000
#define HH 256
#define BB 128
#define VV 4
#define CC 10
#define PH 512                // pair row width: 2 views * 256 feats
#define KC 32                 // gemm k-chunk
#define SCB 49                // scan blocks: 49*1024 >= NN

// ---- scratch (device globals; no allocation allowed) ----
__device__ int    g_degcnt[NN];
__device__ int    g_rowptr[NN+1];
__device__ int    g_fill[NN];
__device__ float  g_invdeg[NN];
__device__ int    g_col[EE];
__device__ int    g_counts[BB];
__device__ int    g_part[SCB];              // scan partials
__device__ float4 g_mask4[NN];              // transposed node masks
__device__ __half g_w1h[HH*HH];             // W1 fp16
__device__ __half g_z[NPAD*HH];             // (x*dropout) @ W1, fp16
__device__ __half g_pairs[2][(size_t)NN*PH]; // view pairs {0,1},{2,3}
__device__ __half g_ptmp[2][(size_t)NN*PH];  // ping-pong per pair
__device__ float  g_pool[VV*BB*HH];
__device__ float  g_probs[VV*BB*CC];

// ---------------------------------------------------------------------------
// zero counters + convert W1 to fp16 (no dependency between the two)
__global__ void k_zero(const float* __restrict__ W1) {
    int i = blockIdx.x * blockDim.x + threadIdx.x;
    if (i < NN) g_degcnt[i] = 0;
    if (i < BB) g_counts[i] = 0;
    if (i < VV*BB*HH) g_pool[i] = 0.f;
    if (i < HH*HH/4) {
        float4 w = *(const float4*)(W1 + i * 4);
        __half2 h[2];
        h[0] = __floats2half2_rn(w.x, w.y);
        h[1] = __floats2half2_rn(w.z, w.w);
        *(uint2*)(g_w1h + i * 4) = *(uint2*)h;
    }
}

// histogram over edge rows + batch counts + mask transpose, one launch
__global__ void k_hist(const int* __restrict__ ei, const int* __restrict__ batch,
                       const float* __restrict__ masks) {
    int e = blockIdx.x * blockDim.x + threadIdx.x;
    if (e < EE) {
        int r = ei[e];
        if ((unsigned)r < NN) atomicAdd(&g_degcnt[r], 1);
    }
    if (e < NN) {
        int b = batch[e];
        if ((unsigned)b < BB) atomicAdd(&g_counts[b], 1);
        g_mask4[e] = make_float4(masks[e], masks[NN + e], masks[2*NN + e], masks[3*NN + e]);
    }
}

// ---- 3-phase grid-wide exclusive scan of g_degcnt -------------------------
// phase a: per-block sums (coalesced, one element/thread)
__global__ __launch_bounds__(1024) void k_scan_a() {
    __shared__ int wsum[32];
    int i = blockIdx.x * 1024 + threadIdx.x;
    int lane = threadIdx.x & 31, wid = threadIdx.x >> 5;
    int c = (i < NN) ? g_degcnt[i] : 0;
    int s = c;
    #pragma unroll
    for (int d = 16; d > 0; d >>= 1) s += __shfl_down_sync(0xffffffffu, s, d);
    if (lane == 0) wsum[wid] = s;
    __syncthreads();
    if (wid == 0) {
        int t = wsum[lane];
        #pragma unroll
        for (int d = 16; d > 0; d >>= 1) t += __shfl_down_sync(0xffffffffu, t, d);
        if (lane == 0) g_part[blockIdx.x] = t;
    }
}

// phase b: exclusive scan of SCB partials; grand total -> g_rowptr[NN]
__global__ void k_scan_b() {
    __shared__ int w0[2];
    int tid = threadIdx.x;          // 64 threads
    int lane = tid & 31, wid = tid >> 5;
    int v = (tid < SCB) ? g_part[tid] : 0;
    int inc = v;
    #pragma unroll
    for (int d = 1; d < 32; d <<= 1) {
        int t = __shfl_up_sync(0xffffffffu, inc, d);
        if (lane >= d) inc += t;
    }
    if (lane == 31) w0[wid] = inc;
    __syncthreads();
    int off = (wid == 1) ? w0[0] : 0;
    if (tid < SCB) g_part[tid] = off + inc - v;   // exclusive
    if (tid == 63) g_rowptr[NN] = w0[0] + w0[1];
}

// phase c: block-exclusive scan + partial offset -> rowptr/fill/invdeg
__global__ __launch_bounds__(1024) void k_scan_c() {
    __shared__ int winc[32];
    __shared__ int woff[32];
    int i = blockIdx.x * 1024 + threadIdx.x;
    int lane = threadIdx.x & 31, wid = threadIdx.x >> 5;
    int c = (i < NN) ? g_degcnt[i] : 0;
    int inc = c;
    #pragma unroll
    for (int d = 1; d < 32; d <<= 1) {
        int t = __shfl_up_sync(0xffffffffu, inc, d);
        if (lane >= d) inc += t;
    }
    if (lane == 31) winc[wid] = inc;
    __syncthreads();
    if (wid == 0) {
        int v = winc[lane];
        int vi = v;
        #pragma unroll
        for (int d = 1; d < 32; d <<= 1) {
            int t = __shfl_up_sync(0xffffffffu, vi, d);
            if (lane >= d) vi += t;
        }
        woff[lane] = vi - v;
    }
    __syncthreads();
    if (i < NN) {
        int run = g_part[blockIdx.x] + woff[wid] + (inc - c);
        g_rowptr[i] = run;
        g_fill[i]   = run;
        g_invdeg[i] = 1.0f / (float)(c + 1);
    }
}

__global__ void k_fill(const int* __restrict__ ei) {
    int e = blockIdx.x * blockDim.x + threadIdx.x;
    if (e < EE) {
        int r = ei[e];
        int c = ei[EE + e];
        if ((unsigned)r < NN && (unsigned)c < NN) {
            int p = atomicAdd(&g_fill[r], 1);
            if ((unsigned)p < EE) g_col[p] = c;
        }
    }
}

// ---------------------------------------------------------------------------
// Fused dropout-multiply + fp16 convert + GEMM:  z = (x*dm) @ W1
__global__ __launch_bounds__(256) void k_gemm_fused(const float* __restrict__ x,
                                                    const float* __restrict__ dm) {
    __shared__ __align__(16) __half As[64][KC + 8];
    __shared__ __align__(16) __half Bs[KC][HH + 8];
    int tid = threadIdx.x;
    int warp = tid >> 5, lane = tid & 31;
    int wm = warp >> 2;
    int wn = warp & 3;
    int m0 = blockIdx.x * 64;

    wmma::fragment<wmma::accumulator, 16, 16, 16, float> c[2][4];
    #pragma unroll
    for (int i = 0; i < 2; i++)
        #pragma unroll
        for (int j = 0; j < 4; j++) wmma::fill_fragment(c[i][j], 0.f);

    for (int kk = 0; kk < HH; kk += KC) {
        #pragma unroll
        for (int i = 0; i < 2; i++) {
            int idx = tid + i * 256;
            int row = idx >> 3;
            int c4  = (idx & 7) * 4;
            int grow = m0 + row;
            __half2 h0, h1;
            if (grow < NN) {
                float4 xv = *(const float4*)(x  + (size_t)grow * HH + kk + c4);
                float4 dv = *(const float4*)(dm + (size_t)grow * HH + kk + c4);
                h0 = __floats2half2_rn(xv.x*dv.x, xv.y*dv.y);
                h1 = __floats2half2_rn(xv.z*dv.z, xv.w*dv.w);
            } else {
                h0 = __floats2half2_rn(0.f, 0.f);
                h1 = h0;
            }
            *(__half2*)&As[row][c4]     = h0;
            *(__half2*)&As[row][c4 + 2] = h1;
        }
        #pragma unroll
        for (int i = 0; i < 4; i++) {
            int idx = tid + i * 256;
            int row = idx >> 5;
            int c8  = (idx & 31) * 8;
            *(uint4*)&Bs[row][c8] = *(const uint4*)(g_w1h + (size_t)(kk + row) * HH + c8);
        }
        __syncthreads();
        #pragma unroll
        for (int ks = 0; ks < KC; ks += 16) {
            wmma::fragment<wmma::matrix_a, 16, 16, 16, __half, wmma::row_major> a[2];
            #pragma unroll
            for (int i = 0; i < 2; i++)
                wmma::load_matrix_sync(a[i], &As[wm*32 + 16*i][ks], KC + 8);
            #pragma unroll
            for (int j = 0; j < 4; j++) {
                wmma::fragment<wmma::matrix_b, 16, 16, 16, __half, wmma::row_major> b;
                wmma::load_matrix_sync(b, &Bs[ks][wn*64 + 16*j], HH + 8);
                wmma::mma_sync(c[0][j], a[0], b, c[0][j]);
                wmma::mma_sync(c[1][j], a[1], b, c[1][j]);
            }
        }
        __syncthreads();
    }

    float* stg = (float*)Bs + warp * 320;
    #pragma unroll
    for (int i = 0; i < 2; i++)
        #pragma unroll
        for (int j = 0; j < 4; j++) {
            wmma::store_matrix_sync(stg, c[i][j], 20, wmma::mem_row_major);
            __syncwarp();
            if (lane < 16) {
                const float* sr = stg + lane * 20;
                __half2 hh[8];
                #pragma unroll
                for (int p = 0; p < 8; p++)
                    hh[p] = __floats2half2_rn(sr[2*p], sr[2*p+1]);
                int gr = m0 + wm*32 + i*16 + lane;
                __half* dst = g_z + (size_t)gr * HH + wn*64 + j*16;
                ((uint4*)dst)[0] = ((uint4*)hh)[0];
                ((uint4*)dst)[1] = ((uint4*)hh)[1];
            }
            __syncwarp();
        }
}

// ---------------------------------------------------------------------------
__device__ __forceinline__ void load_row8(const __half* base, int lane, float f[8]) {
    uint4 raw = ((const uint4*)base)[lane];
    __half2* h = (__half2*)&raw;
    float2 t;
    t = __half22float2(h[0]); f[0] = t.x; f[1] = t.y;
    t = __half22float2(h[1]); f[2] = t.x; f[3] = t.y;
    t = __half22float2(h[2]); f[4] = t.x; f[5] = t.y;
    t = __half22float2(h[3]); f[6] = t.x; f[7] = t.y;
}
// evict-first store: output rows are not re-read within the pass
__device__ __forceinline__ void store_row8_cs(__half* base, int lane, const float f[8], float scale) {
    __half2 h[4];
    #pragma unroll
    for (int p = 0; p < 4; p++)
        h[p] = __floats2half2_rn(f[2*p] * scale, f[2*p+1] * scale);
    __stcs((uint4*)base + lane, *(uint4*)h);
}

// Fused first propagation step for all 4 views; writes pair layouts.
__global__ __launch_bounds__(256) void k_step1() {
    int gw = (blockIdx.x * blockDim.x + threadIdx.x) >> 5;
    int lane = threadIdx.x & 31;
    if (gw >= NN) return;
    int r = gw;

    float s[8];
    load_row8(g_z + (size_t)r * HH, lane, s);

    float4 mr = g_mask4[r];
    float mm[VV] = {mr.x, mr.y, mr.z, mr.w};
    float a[VV][8];
    #pragma unroll
    for (int v = 0; v < VV; v++)
        #pragma unroll
        for (int q = 0; q < 8; q++) a[v][q] = s[q] * mm[v];

    int jb = g_rowptr[r], je = g_rowptr[r + 1];
    for (int j = jb; j < je; j++) {
        int c = g_col[j];
        float cf[8];
        load_row8(g_z + (size_t)c * HH, lane, cf);
        float4 mc = g_mask4[c];
        float mv[VV] = {mc.x, mc.y, mc.z, mc.w};
        #pragma unroll
        for (int v = 0; v < VV; v++)
            #pragma unroll
            for (int q = 0; q < 8; q++) a[v][q] += mv[v] * cf[q];
    }
    float inv = g_invdeg[r];
    #pragma unroll
    for (int v = 0; v < VV; v++)
        store_row8_cs(g_pairs[v >> 1] + (size_t)r * PH + (v & 1) * HH, lane, a[v], inv);
}

// one propagation step for one view-pair; dir=0: pairs->ptmp, dir=1: ptmp->pairs
__global__ __launch_bounds__(256) void k_spmm2(int pair, int dir) {
    const __half* in = dir ? g_ptmp[pair] : g_pairs[pair];
    __half* out      = dir ? g_pairs[pair] : g_ptmp[pair];

    int gw = (blockIdx.x * blockDim.x + threadIdx.x) >> 5;
    int lane = threadIdx.x & 31;
    if (gw >= NN) return;
    int r = gw;

    float a0[8], a1[8];
    const __half* srow = in + (size_t)r * PH;
    load_row8(srow,      lane, a0);
    load_row8(srow + HH, lane, a1);

    int jb = g_rowptr[r], je = g_rowptr[r + 1];
    int j = jb;
    for (; j + 1 < je; j += 2) {
        int c0 = g_col[j], c1 = g_col[j + 1];
        const __half* p0 = in + (size_t)c0 * PH;
        const __half* p1 = in + (size_t)c1 * PH;
        float u0[8], u1[8], w0[8], w1[8];
        load_row8(p0,      lane, u0);
        load_row8(p0 + HH, lane, u1);
        load_row8(p1,      lane, w0);
        load_row8(p1 + HH, lane, w1);
        #pragma unroll
        for (int q = 0; q < 8; q++) { a0[q] += u0[q] + w0[q]; a1[q] += u1[q] + w1[q]; }
    }
    if (j < je) {
        int c = g_col[j];
        const __half* p = in + (size_t)c * PH;
        float u0[8], u1[8];
        load_row8(p,      lane, u0);
        load_row8(p + HH, lane, u1);
        #pragma unroll
        for (int q = 0; q < 8; q++) { a0[q] += u0[q]; a1[q] += u1[q]; }
    }
    float inv = g_invdeg[r];
    __half* orow = out + (size_t)r * PH;
    store_row8_cs(orow,      lane, a0, inv);
    store_row8_cs(orow + HH, lane, a1, inv);
}

// ---------------------------------------------------------------------------
// pooled[v][b][f] += relu(state[r][v][f] + b1[f]) for batch[r]==b
__global__ __launch_bounds__(256) void k_pool(const int* __restrict__ batch,
                                              const float* __restrict__ b1) {
    int v  = blockIdx.y;
    int f  = threadIdx.x;
    int r0 = blockIdx.x * 64;
    const __half* in = g_pairs[v >> 1] + (size_t)(v & 1) * HH;
    float bias = b1[f];
    float acc = 0.f;
    int curb = -1;
    int rend = r0 + 64; if (rend > NN) rend = NN;
    for (int r = r0; r < rend; r++) {
        int b = batch[r];
        if ((unsigned)b >= BB) continue;
        if (b != curb) {
            if (curb >= 0) atomicAdd(&g_pool[(curb + v * BB) * HH + f], acc);
            acc = 0.f; curb = b;
        }
        float val = __half2float(in[(size_t)r * PH + f]) + bias;
        acc += fmaxf(val, 0.f);
    }
    if (curb >= 0) atomicAdd(&g_pool[(curb + v * BB) * HH + f], acc);
}

__global__ __launch_bounds__(256) void k_head(const float* __restrict__ W2,
                                              const float* __restrict__ b2,
                                              const float* __restrict__ Wc,
                                              const float* __restrict__ bcv,
                                              float* __restrict__ out) {
    __shared__ float sp[HH];
    __shared__ float sy[HH];
    __shared__ float slog[CC];
    int vb = blockIdx.x;
    int v = vb >> 7, b = vb & 127;
    int tid = threadIdx.x;

    float cnt = (float)g_counts[b];
    if (cnt < 1.f) cnt = 1.f;
    sp[tid] = g_pool[(v * BB + b) * HH + tid] / cnt;
    __syncthreads();

    float acc = b2[tid];
    #pragma unroll 8
    for (int h = 0; h < HH; h++) acc += sp[h] * W2[h * HH + tid];
    sy[tid] = acc;
    __syncthreads();

    if (tid < CC) {
        float l = bcv[tid];
        #pragma unroll 8
        for (int h = 0; h < HH; h++) l += sy[h] * Wc[h * CC + tid];
        slog[tid] = l;
    }
    __syncthreads();

    if (tid == 0) {
        float mx = -1e30f;
        #pragma unroll
        for (int c = 0; c < CC; c++) mx = fmaxf(mx, slog[c]);
        float s = 0.f, e[CC];
        #pragma unroll
        for (int c = 0; c < CC; c++) { e[c] = expf(slog[c] - mx); s += e[c]; }
        float invs = 1.f / s;
        #pragma unroll
        for (int c = 0; c < CC; c++) g_probs[(v * BB + b) * CC + c] = e[c] * invs;
        if (v == 0) {
            #pragma unroll
            for (int c = 0; c < CC; c++) out[b * CC + c] = slog[c];
        }
    }
}

__global__ void k_loss(float* __restrict__ out, int out_size) {
    __shared__ float sc[BB], se[BB];
    int b = threadIdx.x;
    float mp[CC];
    #pragma unroll
    for (int c = 0; c < CC; c++) {
        float s = 0.f;
        #pragma unroll
        for (int v = 0; v < VV; v++) s += g_probs[(v * BB + b) * CC + c];
        mp[c] = s * (1.0f / VV);
    }
    float cons = 0.f;
    #pragma unroll
    for (int v = 0; v < VV; v++)
        #pragma unroll
        for (int c = 0; c < CC; c++) {
            float d = g_probs[(v * BB + b) * CC + c] - mp[c];
            cons += d * d;
        }
    float ent = 0.f;
    #pragma unroll
    for (int c = 0; c < CC; c++) ent -= mp[c] * logf(mp[c] + 1e-8f);
    sc[b] = cons; se[b] = ent;
    __syncthreads();
    for (int s = 64; s > 0; s >>= 1) {
        if (b < s) { sc[b] += sc[b + s]; se[b] += se[b + s]; }
        __syncthreads();
    }
    if (b == 0)
        out[out_size - 1] = 1.0f * (sc[0] / (float)(VV * BB)) + se[0] / (float)BB;
}

// ---------------------------------------------------------------------------
extern "C" void kernel_launch(void* const* d_in, const int* in_sizes, int n_in,
                              void* d_out, int out_size) {
    const float* x     = (const float*)d_in[0];
    const int*   ei    = (const int*)d_in[1];
    const int*   batch = (const int*)d_in[2];
    const float* dm    = (const float*)d_in[3];
    const float* masks = (const float*)d_in[4];
    const float* W1    = (const float*)d_in[5];
    const float* b1    = (const float*)d_in[6];
    const float* W2    = (const float*)d_in[7];
    const float* b2    = (const float*)d_in[8];
    const float* Wc    = (const float*)d_in[9];
    const float* bcv   = (const float*)d_in[10];
    float* out = (float*)d_out;

    // fork/join: CSR chain on capture stream, GEMM on side stream.
    cudaStream_t s2;
    cudaStreamCreate(&s2);
    cudaEvent_t eFork, eJoin;
    cudaEventCreateWithFlags(&eFork, cudaEventDisableTiming);
    cudaEventCreateWithFlags(&eJoin, cudaEventDisableTiming);

    k_zero<<<(VV*BB*HH + 255) / 256, 256>>>(W1);
    cudaEventRecord(eFork, 0);
    cudaStreamWaitEvent(s2, eFork, 0);

    k_gemm_fused<<<NPAD / 64, 256, 0, s2>>>(x, dm);   // side stream
    cudaEventRecord(eJoin, s2);

    k_hist<<<(EE + 255) / 256, 256>>>(ei, batch, masks);
    k_scan_a<<<SCB, 1024>>>();
    k_scan_b<<<1, 64>>>();
    k_scan_c<<<SCB, 1024>>>();
    k_fill<<<(EE + 255) / 256, 256>>>(ei);

    cudaStreamWaitEvent(0, eJoin, 0);                 // join before step1

    int wgrid = (NN * 32 + 255) / 256;
    k_step1<<<wgrid, 256>>>();
    k_spmm2<<<wgrid, 256>>>(0, 0);   // pair0 step2
    k_spmm2<<<wgrid, 256>>>(0, 1);   // pair0 step3
    k_spmm2<<<wgrid, 256>>>(1, 0);   // pair1 step2
    k_spmm2<<<wgrid, 256>>>(1, 1);   // pair1 step3

    dim3 pgrid((NN + 63) / 64, VV);
    k_pool<<<pgrid, 256>>>(batch, b1);

    k_head<<<VV * BB, 256>>>(W2, b2, Wc, bcv, out);
    k_loss<<<1, BB>>>(out, out_size);
}